// round 9
// baseline (speedup 1.0000x reference)
#include <cuda_runtime.h>
#include <cuda_bf16.h>
#include <cstdint>
#include <cstddef>

// Problem constants
constexpr int EB   = 1024;
constexpr int NBAT = 16;
constexpr int SEQ  = 1024;
constexpr int NLAY = 12;
constexpr int MTOT = NBAT * SEQ;   // 16384
constexpr int AD   = 10;
constexpr int DA   = 640;
constexpr int HORZ = 512;

typedef __nv_bfloat16 bf16;

// Does this compilation pass support arch-specific sm_103a instructions?
#if defined(__CUDA_ARCH__) && (defined(__CUDA_ARCH_FEAT_SM103_ALL) || \
    (defined(__CUDA_ARCH_SPECIFIC__)) || (defined(__CUDA_ARCH_FAMILY_SPECIFIC__)))
#define TC_OK 1
#else
#define TC_OK 0
#endif

// ---------------- scratch (device globals; no allocations allowed) ----------
__device__ float d_Hs[(size_t)MTOT * EB];
__device__ float d_T [(size_t)MTOT * EB];
__device__ float d_aW[(size_t)NBAT * EB];

__device__ bf16 d_Hh[(size_t)MTOT * EB],  d_Hl[(size_t)MTOT * EB];
__device__ bf16 d_Qh[(size_t)MTOT * EB],  d_Ql[(size_t)MTOT * EB];
__device__ bf16 d_Kh[(size_t)MTOT * EB],  d_Kl[(size_t)MTOT * EB];
__device__ bf16 d_Vth[(size_t)MTOT * EB], d_Vtl[(size_t)MTOT * EB];
__device__ bf16 d_Sh[(size_t)NBAT * SEQ * SEQ], d_Sl[(size_t)NBAT * SEQ * SEQ];
__device__ bf16 d_Wq_h[(size_t)NLAY * EB * EB], d_Wq_l[(size_t)NLAY * EB * EB];
__device__ bf16 d_Wk_h[(size_t)NLAY * EB * EB], d_Wk_l[(size_t)NLAY * EB * EB];
__device__ bf16 d_Wv_h[(size_t)NLAY * EB * EB], d_Wv_l[(size_t)NLAY * EB * EB];
__device__ bf16 d_W1_h[(size_t)NLAY * EB * EB], d_W1_l[(size_t)NLAY * EB * EB];
__device__ bf16 d_W2_h[(size_t)NLAY * EB * EB], d_W2_l[(size_t)NLAY * EB * EB];

// ---------------- common helpers --------------------------------------------
__device__ __forceinline__ uint32_t cvs(const void* p) {
    return (uint32_t)__cvta_generic_to_shared(p);
}
__device__ __forceinline__ void split1(float x, bf16& h, bf16& l) {
    h = __float2bfloat16(x);
    l = __float2bfloat16(x - __bfloat162float(h));
}
#define CPA(dst, src) asm volatile("cp.async.cg.shared.global [%0],[%1],16;\n" :: "r"(dst), "l"(src))
#define CP_COMMIT()   asm volatile("cp.async.commit_group;\n")
#define CP_WAIT0()    asm volatile("cp.async.wait_group 0;\n")
#define CP_WAIT1()    asm volatile("cp.async.wait_group 1;\n")

// legacy mma.sync helpers (valid on all passes)
__device__ __forceinline__ void ldsm4(uint32_t* r, uint32_t addr) {
    asm volatile("ldmatrix.sync.aligned.m8n8.x4.shared.b16 {%0,%1,%2,%3},[%4];"
                 : "=r"(r[0]), "=r"(r[1]), "=r"(r[2]), "=r"(r[3]) : "r"(addr));
}
__device__ __forceinline__ void mma16816(float* d, const uint32_t* a,
                                         uint32_t b0, uint32_t b1) {
    asm volatile("mma.sync.aligned.m16n8k16.row.col.f32.bf16.bf16.f32 "
                 "{%0,%1,%2,%3},{%4,%5,%6,%7},{%8,%9},{%0,%1,%2,%3};"
                 : "+f"(d[0]), "+f"(d[1]), "+f"(d[2]), "+f"(d[3])
                 : "r"(a[0]), "r"(a[1]), "r"(a[2]), "r"(a[3]), "r"(b0), "r"(b1));
}

#if TC_OK
// ---------------- tcgen05 helpers (sm_103a-specific pass only) --------------
__device__ __forceinline__ uint32_t elect1() {
    uint32_t pred;
    asm volatile("{\n\t.reg .pred p;\n\telect.sync _|p, 0xFFFFFFFF;\n\t"
                 "selp.b32 %0, 1, 0, p;\n\t}" : "=r"(pred));
    return pred;
}
__device__ __forceinline__ uint64_t mk_desc(uint32_t base_addr) {
    constexpr uint64_t BASE =
        (uint64_t(2) << 61) | (uint64_t(1) << 46) | (uint64_t(64) << 32) | (uint64_t(1) << 16);
    return BASE | ((uint64_t)(base_addr >> 4) & 0x3FFF);
}
__device__ __forceinline__ void mma_f16_ss(uint32_t d, uint64_t ad, uint64_t bd,
                                           uint32_t idesc, uint32_t en) {
    asm volatile(
        "{\n\t.reg .pred p;\n\tsetp.ne.u32 p, %5, 0;\n\t"
        "tcgen05.mma.cta_group::1.kind::f16 [%0], %1, %2, %3, {%4,%4,%4,%4}, p;\n\t}"
        :: "r"(d), "l"(ad), "l"(bd), "r"(idesc), "r"(0u), "r"(en) : "memory");
}
__device__ __forceinline__ void tc_commit(uint32_t mbar) {
    asm volatile("tcgen05.commit.cta_group::1.mbarrier::arrive::one.shared::cluster.b64 [%0];"
                 :: "r"(mbar) : "memory");
}
__device__ __forceinline__ void mbar_init(uint32_t a, uint32_t cnt) {
    asm volatile("mbarrier.init.shared.b64 [%0], %1;" :: "r"(a), "r"(cnt) : "memory");
}
__device__ __forceinline__ void mbar_wait(uint32_t a, uint32_t parity) {
    asm volatile(
        "{\n\t.reg .pred P;\n\tW%=:\n\t"
        "mbarrier.try_wait.parity.acquire.cta.shared::cta.b64 P, [%0], %1, 0x989680;\n\t"
        "@!P bra W%=;\n\t}" :: "r"(a), "r"(parity) : "memory");
}
// arrive (WITHOUT incrementing pending count) when this thread's prior
// cp.asyncs complete. .noinc is load-bearing: the default variant increments
// the pending count before arriving (net zero) and deadlocks this protocol.
__device__ __forceinline__ void cp_mbar_arrive(uint32_t mbar) {
    asm volatile("cp.async.mbarrier.arrive.noinc.shared::cta.b64 [%0];"
                 :: "r"(mbar) : "memory");
}
__device__ __forceinline__ void ld_tm32(uint32_t* r, uint32_t addr) {
    asm volatile(
        "tcgen05.ld.sync.aligned.32x32b.x32.b32 "
        "{%0,%1,%2,%3,%4,%5,%6,%7,%8,%9,%10,%11,%12,%13,%14,%15,"
        "%16,%17,%18,%19,%20,%21,%22,%23,%24,%25,%26,%27,%28,%29,%30,%31},[%32];"
        : "=r"(r[0]), "=r"(r[1]), "=r"(r[2]), "=r"(r[3]), "=r"(r[4]), "=r"(r[5]),
          "=r"(r[6]), "=r"(r[7]), "=r"(r[8]), "=r"(r[9]), "=r"(r[10]), "=r"(r[11]),
          "=r"(r[12]), "=r"(r[13]), "=r"(r[14]), "=r"(r[15]), "=r"(r[16]), "=r"(r[17]),
          "=r"(r[18]), "=r"(r[19]), "=r"(r[20]), "=r"(r[21]), "=r"(r[22]), "=r"(r[23]),
          "=r"(r[24]), "=r"(r[25]), "=r"(r[26]), "=r"(r[27]), "=r"(r[28]), "=r"(r[29]),
          "=r"(r[30]), "=r"(r[31])
        : "r"(addr));
}
#define TC_WAIT_LD()     asm volatile("tcgen05.wait::ld.sync.aligned;" ::: "memory")
#define TC_FENCE_AFTER() asm volatile("tcgen05.fence::after_thread_sync;" ::: "memory")
#define FENCE_ASYNC()    asm volatile("fence.proxy.async.shared::cta;" ::: "memory")
#endif  // TC_OK

// ---------------------------------------------------------------------------
// GEMM: C[M,N] = (Ah+Al)[M,K] @ (Bh+Bl)[N,K]^T  (3-term bf16x3, fp32 acc)
// tcgen05 path: CTA tile 128x128, BK=64 (SW128 rows), 3-stage fully-async
// pipeline (cp.async.mbarrier.arrive.noinc full[] barriers + tcgen05.commit
// done[] barriers; NO per-tile __syncthreads).
// fallback path: mma.sync m16n8k16 (compile-only; tcgen05 wins fatbin dispatch)
// ---------------------------------------------------------------------------
constexpr int BM = 128, BN = 128;

// tcgen05 layout
constexpr int TC_BK   = 64;
constexpr int TC_PL   = BM * 128;           // plane bytes = 16384
constexpr int TC_STG  = 4 * TC_PL;          // stage bytes = 65536
constexpr int TC_HDR  = 1024;
constexpr int TC_NSTG = 3;
constexpr uint32_t IDESC =
    (1u << 4) | (1u << 7) | (1u << 10) | ((BN / 8) << 17) | ((BM / 16) << 24);
constexpr int TMEM_COLS_ALLOC = 128;

// fallback layout
constexpr int FB_BK  = 32;
constexpr int FB_PL  = BM * 40 * 2;       // 10240
constexpr int FB_STG = 4 * FB_PL;         // 40960
constexpr int FB_STAGES = 3;

constexpr int SMB = 1024 + TC_HDR + TC_NSTG * TC_STG;   // 198656

enum { EPI_NONE = 0, EPI_BIAS = 1, EPI_SPLIT = 2, EPI_BR_SPLIT = 3, EPI_SC_SPLIT = 4 };

#if TC_OK
__device__ __forceinline__ void tc_load_stage(uint32_t stgBase,
    const bf16* __restrict__ Ah, const bf16* __restrict__ Al,
    const bf16* __restrict__ Bh, const bf16* __restrict__ Bl,
    int K, int k0, int row0, int col0, int tid)
{
    const int r = tid >> 1;
    const int h = tid & 1;
    const size_t gA = (size_t)(row0 + r) * K + k0 + h * 32;
    const size_t gB = (size_t)(col0 + r) * K + k0 + h * 32;
    #pragma unroll
    for (int c = 0; c < 4; c++) {
        uint32_t off = (uint32_t)r * 128 + h * 64 + c * 16;
        uint32_t sw  = off ^ ((off >> 3) & 0x70);
        CPA(stgBase + 0 * TC_PL + sw, Ah + gA + c * 8);
        CPA(stgBase + 1 * TC_PL + sw, Al + gA + c * 8);
        CPA(stgBase + 2 * TC_PL + sw, Bh + gB + c * 8);
        CPA(stgBase + 3 * TC_PL + sw, Bl + gB + c * 8);
    }
}
#endif

__device__ __forceinline__ void fb_load_stage(uint32_t smBase,
    const bf16* __restrict__ Agh, const bf16* __restrict__ Agl,
    const bf16* __restrict__ Bgh, const bf16* __restrict__ Bgl,
    int K, int k0, int row0, int col0, int tid)
{
    const int row = tid >> 1;
    const int half = tid & 1;
    const uint32_t sm = smBase + row * 80 + half * 32;
    const size_t gA = (size_t)(row0 + row) * K + k0 + half * 16;
    const size_t gB = (size_t)(col0 + row) * K + k0 + half * 16;
    CPA(sm,                  Agh + gA); CPA(sm + 16,                  Agh + gA + 8);
    CPA(sm + FB_PL,          Agl + gA); CPA(sm + FB_PL + 16,          Agl + gA + 8);
    CPA(sm + 2 * FB_PL,      Bgh + gB); CPA(sm + 2 * FB_PL + 16,      Bgh + gB + 8);
    CPA(sm + 3 * FB_PL,      Bgl + gB); CPA(sm + 3 * FB_PL + 16,      Bgl + gB + 8);
}

template<int EPI, bool KLIM>
__global__ void __launch_bounds__(256, 1)
gemm_k(const bf16* __restrict__ Agh, const bf16* __restrict__ Agl,
       const bf16* __restrict__ Bgh, const bf16* __restrict__ Bgl,
       const float* __restrict__ bias,
       float* __restrict__ Cg, bf16* __restrict__ Chg, bf16* __restrict__ Clg,
       int N, int K, size_t sA, size_t sB, size_t sC)
{
    extern __shared__ char smem[];

    const int bx = blockIdx.x, by = blockIdx.y, bz = blockIdx.z;
    const int tid = threadIdx.x;
    const int lane = tid & 31, wid = tid >> 5;
    const int row0 = by * BM, col0 = bx * BN;

    // Score tiles strictly above the causal diagonal are NEVER read by the
    // S@V GEMM (its K-loop is clamped to (by+1)*BM), so skip entirely.
    if (EPI == EPI_SC_SPLIT && col0 >= row0 + BM) return;

    const bf16* Ah = Agh + (size_t)bz * sA;
    const bf16* Al = Agl + (size_t)bz * sA;
    const bf16* Bh = Bgh + (size_t)bz * sB;
    const bf16* Bl = Bgl + (size_t)bz * sB;

    int Keff = K;
    if (KLIM) { int km = (by + 1) * BM; Keff = km < K ? km : K; }

#if TC_OK
    // ======================= tcgen05 body ====================================
    const uint32_t sbRaw = cvs(smem);
    const uint32_t sb = (sbRaw + 1023u) & ~1023u;
    // header layout: [0] tmem ptr, [8/16/24] done mbars, [32/40/48] full mbars
    const uint32_t mDone = sb + 8, mFull = sb + 32;

    if (wid == 0)
        asm volatile("tcgen05.alloc.cta_group::1.sync.aligned.shared::cta.b32 [%0], %1;"
                     :: "r"(sb), "r"((uint32_t)TMEM_COLS_ALLOC) : "memory");
    if (tid == 0) {
        mbar_init(mDone + 0, 1);  mbar_init(mDone + 8, 1);  mbar_init(mDone + 16, 1);
        mbar_init(mFull + 0, 256); mbar_init(mFull + 8, 256); mbar_init(mFull + 16, 256);
    }
    __syncthreads();
    uint32_t tbase;
    asm volatile("ld.shared.b32 %0, [%1];" : "=r"(tbase) : "r"(sb));
    if (wid == 0)
        asm volatile("tcgen05.relinquish_alloc_permit.cta_group::1.sync.aligned;");

    const int NT = Keff / TC_BK;   // >= 2 for all our shapes

    // prologue: stages 0 and 1 (each .noinc arrive fires when this thread's
    // prior cp.asyncs complete; 256 arrives flip the barrier)
    tc_load_stage(sb + TC_HDR,          Ah, Al, Bh, Bl, K, 0,     row0, col0, tid);
    cp_mbar_arrive(mFull + 0);
    tc_load_stage(sb + TC_HDR + TC_STG, Ah, Al, Bh, Bl, K, TC_BK, row0, col0, tid);
    cp_mbar_arrive(mFull + 8);

    uint32_t phF = 0, phD = 0;     // per-buffer phase bits (per-thread)

    for (int t = 0; t < NT; t++) {
        const int b = t % TC_NSTG;

        if (wid == 0) {
            // consume full[b]
            mbar_wait(mFull + b * 8, (phF >> b) & 1);
            phF ^= 1u << b;
            FENCE_ASYNC();
            TC_FENCE_AFTER();
            if (elect1()) {
                const uint32_t stg = sb + TC_HDR + b * TC_STG;
                const uint64_t adh = mk_desc(stg);
                const uint64_t adl = mk_desc(stg + TC_PL);
                const uint64_t bdh = mk_desc(stg + 2 * TC_PL);
                const uint64_t bdl = mk_desc(stg + 3 * TC_PL);
                #pragma unroll
                for (int ks = 0; ks < 4; ks++) {
                    uint32_t en0 = (t > 0 || ks > 0) ? 1u : 0u;
                    mma_f16_ss(tbase, adh + ks * 2, bdh + ks * 2, IDESC, en0);
                    mma_f16_ss(tbase, adh + ks * 2, bdl + ks * 2, IDESC, 1u);
                    mma_f16_ss(tbase, adl + ks * 2, bdh + ks * 2, IDESC, 1u);
                }
                tc_commit(mDone + b * 8);
            }
        }

        if (t + 2 < NT) {
            const int nb = (t + 2) % TC_NSTG;
            if (t >= 1) {   // buffer nb was consumed by MMA(t-1): wait its commit
                mbar_wait(mDone + nb * 8, (phD >> nb) & 1);
                phD ^= 1u << nb;
            }
            tc_load_stage(sb + TC_HDR + nb * TC_STG, Ah, Al, Bh, Bl, K,
                          (t + 2) * TC_BK, row0, col0, tid);
            cp_mbar_arrive(mFull + nb * 8);
        }
    }

    // final MMA completion (commit tracks all prior MMAs from this CTA)
    const int lb = (NT - 1) % TC_NSTG;
    mbar_wait(mDone + lb * 8, (phD >> lb) & 1);
    TC_FENCE_AFTER();

    // epilogue: warp w -> rows (w&3)*32+lane, cols (w>>2)*64 .. +63
    {
        const int wq = wid & 3;
        const int colh = (wid >> 2) * 64;
        const uint32_t toff = tbase + ((uint32_t)wq << 21) + (uint32_t)colh;
        const int r = row0 + wq * 32 + lane;

        uint32_t dr[64];
        ld_tm32(dr,      toff);
        ld_tm32(dr + 32, toff + 32);
        TC_WAIT_LD();

        const int cbase = col0 + colh;
        if (EPI == EPI_NONE || EPI == EPI_BIAS) {
            float* C = Cg + (size_t)bz * sC + (size_t)r * N + cbase;
            #pragma unroll
            for (int j = 0; j < 64; j += 4) {
                float4 v;
                v.x = __uint_as_float(dr[j + 0]);
                v.y = __uint_as_float(dr[j + 1]);
                v.z = __uint_as_float(dr[j + 2]);
                v.w = __uint_as_float(dr[j + 3]);
                if (EPI == EPI_BIAS) {
                    v.x += bias[cbase + j];     v.y += bias[cbase + j + 1];
                    v.z += bias[cbase + j + 2]; v.w += bias[cbase + j + 3];
                }
                *(float4*)&C[j] = v;
            }
        } else {
            bf16* Ch = Chg + (size_t)bz * sC + (size_t)r * N + cbase;
            bf16* Cl = Clg + (size_t)bz * sC + (size_t)r * N + cbase;
            float inv = (EPI == EPI_SC_SPLIT) ? 1.0f / (float)(r + 1) : 0.f;
            #pragma unroll
            for (int j = 0; j < 64; j += 2) {
                float x0 = __uint_as_float(dr[j]);
                float x1 = __uint_as_float(dr[j + 1]);
                if (EPI == EPI_BR_SPLIT) {
                    x0 = fmaxf(x0 + bias[cbase + j], 0.f);
                    x1 = fmaxf(x1 + bias[cbase + j + 1], 0.f);
                } else if (EPI == EPI_SC_SPLIT) {
                    x0 = (cbase + j     <= r) ? fmaxf(x0, 0.f) * inv : 0.f;
                    x1 = (cbase + j + 1 <= r) ? fmaxf(x1, 0.f) * inv : 0.f;
                }
                bf16 h0, l0, h1, l1;
                split1(x0, h0, l0); split1(x1, h1, l1);
                __nv_bfloat162 vh; vh.x = h0; vh.y = h1;
                __nv_bfloat162 vl; vl.x = l0; vl.y = l1;
                *(__nv_bfloat162*)&Ch[j] = vh;
                *(__nv_bfloat162*)&Cl[j] = vl;
            }
        }
    }

    __syncthreads();
    if (wid == 0)
        asm volatile("tcgen05.dealloc.cta_group::1.sync.aligned.b32 %0, %1;"
                     :: "r"(tbase), "r"((uint32_t)TMEM_COLS_ALLOC));

#else
    // ======================= mma.sync fallback body ==========================
    const uint32_t smBase = cvs(smem);
    const int NT = Keff / FB_BK;

    float acc[2][8][4];
    #pragma unroll
    for (int i = 0; i < 2; i++)
        #pragma unroll
        for (int j = 0; j < 8; j++)
            #pragma unroll
            for (int q = 0; q < 4; q++) acc[i][j][q] = 0.f;

    const int wm = wid >> 1, wn = wid & 1;
    const int lr = lane & 15;
    const uint32_t colo = (uint32_t)(lane >> 4) * 16;

    #pragma unroll
    for (int s = 0; s < FB_STAGES - 1; s++) {
        if (s < NT) fb_load_stage(smBase + s * FB_STG, Ah, Al, Bh, Bl, K, s * FB_BK, row0, col0, tid);
        CP_COMMIT();
    }

    for (int t = 0; t < NT; t++) {
        CP_WAIT1();
        __syncthreads();

        int tp = t + FB_STAGES - 1;
        if (tp < NT)
            fb_load_stage(smBase + (tp % FB_STAGES) * FB_STG, Ah, Al, Bh, Bl, K, tp * FB_BK, row0, col0, tid);
        CP_COMMIT();

        const uint32_t stg = smBase + (t % FB_STAGES) * FB_STG;
        const uint32_t aRow = stg + (uint32_t)(wm * 32 + lr) * 80 + colo;
        const uint32_t bRow = stg + 2 * FB_PL + (uint32_t)(wn * 64 + lr) * 80 + colo;

        #pragma unroll
        for (int kk = 0; kk < 2; kk++) {
            const uint32_t ka = aRow + kk * 32, kb = bRow + kk * 32;
            uint32_t ah[2][4], al[2][4];
            #pragma unroll
            for (int mf = 0; mf < 2; mf++) {
                ldsm4(ah[mf], ka + mf * 16 * 80);
                ldsm4(al[mf], ka + FB_PL + mf * 16 * 80);
            }
            uint32_t bh[4][4], blf[4][4];
            #pragma unroll
            for (int g = 0; g < 4; g++) {
                ldsm4(bh[g], kb + g * 16 * 80);
                ldsm4(blf[g], kb + FB_PL + g * 16 * 80);
            }
            #pragma unroll
            for (int mf = 0; mf < 2; mf++) {
                #pragma unroll
                for (int g = 0; g < 4; g++) {
                    mma16816(acc[mf][2 * g],     ah[mf], bh[g][0],  bh[g][2]);
                    mma16816(acc[mf][2 * g],     ah[mf], blf[g][0], blf[g][2]);
                    mma16816(acc[mf][2 * g],     al[mf], bh[g][0],  bh[g][2]);
                    mma16816(acc[mf][2 * g + 1], ah[mf], bh[g][1],  bh[g][3]);
                    mma16816(acc[mf][2 * g + 1], ah[mf], blf[g][1], blf[g][3]);
                    mma16816(acc[mf][2 * g + 1], al[mf], bh[g][1],  bh[g][3]);
                }
            }
        }
        __syncthreads();
    }
    CP_WAIT0();

    float*  C  = (EPI == EPI_NONE || EPI == EPI_BIAS) ? Cg + (size_t)bz * sC : nullptr;
    bf16*   Ch = (EPI >= EPI_SPLIT) ? Chg + (size_t)bz * sC : nullptr;
    bf16*   Cl = (EPI >= EPI_SPLIT) ? Clg + (size_t)bz * sC : nullptr;
    const int qr = lane >> 2, qc = (lane & 3) * 2;
    #pragma unroll
    for (int mf = 0; mf < 2; mf++) {
        #pragma unroll
        for (int nf = 0; nf < 8; nf++) {
            int rA = row0 + wm * 32 + mf * 16 + qr;
            int cb = col0 + wn * 64 + nf * 8 + qc;
            #pragma unroll
            for (int half = 0; half < 2; half++) {
                int r = rA + half * 8;
                float x0 = acc[mf][nf][half * 2 + 0];
                float x1 = acc[mf][nf][half * 2 + 1];
                if (EPI == EPI_BIAS) {
                    x0 += bias[cb]; x1 += bias[cb + 1];
                } else if (EPI == EPI_BR_SPLIT) {
                    x0 = fmaxf(x0 + bias[cb], 0.f);
                    x1 = fmaxf(x1 + bias[cb + 1], 0.f);
                } else if (EPI == EPI_SC_SPLIT) {
                    float inv = 1.0f / (float)(r + 1);
                    x0 = (cb     <= r) ? fmaxf(x0, 0.f) * inv : 0.f;
                    x1 = (cb + 1 <= r) ? fmaxf(x1, 0.f) * inv : 0.f;
                }
                if (EPI == EPI_NONE || EPI == EPI_BIAS) {
                    float2 v; v.x = x0; v.y = x1;
                    *(float2*)&C[(size_t)r * N + cb] = v;
                } else {
                    bf16 h0, l0, h1, l1;
                    split1(x0, h0, l0); split1(x1, h1, l1);
                    __nv_bfloat162 vh; vh.x = h0; vh.y = h1;
                    __nv_bfloat162 vl; vl.x = l0; vl.y = l1;
                    *(__nv_bfloat162*)&Ch[(size_t)r * N + cb] = vh;
                    *(__nv_bfloat162*)&Cl[(size_t)r * N + cb] = vl;
                }
            }
        }
    }
#endif
}

// ---------------------------------------------------------------------------
// Transpose + split-convert: in[z][R][C] fp32 -> oh/ol[z][C][R] bf16
// (weights only, once per launch)
// ---------------------------------------------------------------------------
__global__ void convT_k(const float* __restrict__ in, bf16* __restrict__ oh,
                        bf16* __restrict__ ol, int R, int C)
{
    const int z = blockIdx.z;
    in += (size_t)z * R * C;
    oh += (size_t)z * R * C;
    ol += (size_t)z * R * C;
    __shared__ float t[32][33];
    const int c0 = blockIdx.x * 32, r0 = blockIdx.y * 32;
    const int tx = threadIdx.x, ty = threadIdx.y;
    #pragma unroll
    for (int i = 0; i < 4; i++)
        t[ty + i * 8][tx] = in[(size_t)(r0 + ty + i * 8) * C + c0 + tx];
    __syncthreads();
    #pragma unroll
    for (int i = 0; i < 4; i++) {
        float v = t[tx][ty + i * 8];
        int cc = c0 + ty + i * 8, rr = r0 + tx;
        bf16 h, l; split1(v, h, l);
        oh[(size_t)cc * R + rr] = h;
        ol[(size_t)cc * R + rr] = l;
    }
}

// ---------------------------------------------------------------------------
// Fused residual + LayerNorm, emitting fp32 + bf16 hi/lo
// ---------------------------------------------------------------------------
__global__ void ln_k(float* __restrict__ Hs, const float* __restrict__ Res,
                     const float* __restrict__ g, const float* __restrict__ be,
                     bf16* __restrict__ Hh, bf16* __restrict__ Hl)
{
    int row = blockIdx.x;
    int tid = threadIdx.x;
    int lane = tid & 31, warp = tid >> 5;
    __shared__ float sm[8];

    float4 x = *(float4*)&Hs[(size_t)row * EB + tid * 4];
    float4 rr = *(const float4*)&Res[(size_t)row * EB + tid * 4];
    x.x += rr.x; x.y += rr.y; x.z += rr.z; x.w += rr.w;

    float s = x.x + x.y + x.z + x.w;
    #pragma unroll
    for (int o = 16; o; o >>= 1) s += __shfl_down_sync(0xffffffffu, s, o);
    if (!lane) sm[warp] = s;
    __syncthreads();
    float mu;
    {
        float t = (lane < 8) ? sm[lane] : 0.f;
        #pragma unroll
        for (int o = 4; o; o >>= 1) t += __shfl_down_sync(0xffffffffu, t, o);
        mu = __shfl_sync(0xffffffffu, t, 0) * (1.0f / 1024.0f);
    }
    __syncthreads();

    float dx0 = x.x - mu, dx1 = x.y - mu, dx2 = x.z - mu, dx3 = x.w - mu;
    float sq = dx0 * dx0 + dx1 * dx1 + dx2 * dx2 + dx3 * dx3;
    #pragma unroll
    for (int o = 16; o; o >>= 1) sq += __shfl_down_sync(0xffffffffu, sq, o);
    if (!lane) sm[warp] = sq;
    __syncthreads();
    float rstd;
    {
        float t = (lane < 8) ? sm[lane] : 0.f;
        #pragma unroll
        for (int o = 4; o; o >>= 1) t += __shfl_down_sync(0xffffffffu, t, o);
        float var = __shfl_sync(0xffffffffu, t, 0) * (1.0f / 1024.0f);
        rstd = rsqrtf(var + 1e-5f);
    }

    float4 gv = *(const float4*)&g[tid * 4];
    float4 bv = *(const float4*)&be[tid * 4];
    float4 o;
    o.x = dx0 * rstd * gv.x + bv.x;
    o.y = dx1 * rstd * gv.y + bv.y;
    o.z = dx2 * rstd * gv.z + bv.z;
    o.w = dx3 * rstd * gv.w + bv.w;
    *(float4*)&Hs[(size_t)row * EB + tid * 4] = o;

    bf16 h0, l0, h1, l1, h2, l2, h3, l3;
    split1(o.x, h0, l0); split1(o.y, h1, l1);
    split1(o.z, h2, l2); split1(o.w, h3, l3);
    __nv_bfloat162 a0; a0.x = h0; a0.y = h1;
    __nv_bfloat162 a1; a1.x = h2; a1.y = h3;
    __nv_bfloat162 b0; b0.x = l0; b0.y = l1;
    __nv_bfloat162 b1; b1.x = l2; b1.y = l3;
    *(__nv_bfloat162*)&Hh[(size_t)row * EB + tid * 4]     = a0;
    *(__nv_bfloat162*)&Hh[(size_t)row * EB + tid * 4 + 2] = a1;
    *(__nv_bfloat162*)&Hl[(size_t)row * EB + tid * 4]     = b0;
    *(__nv_bfloat162*)&Hl[(size_t)row * EB + tid * 4 + 2] = b1;
}

// ---------------------------------------------------------------------------
// Embedding
// ---------------------------------------------------------------------------
__global__ void aw_k(const float* __restrict__ act, const float* __restrict__ Wemb,
                     float* __restrict__ aW)
{
    int e = blockIdx.x * 128 + threadIdx.x;
    int b = blockIdx.y;
    const float* a = act + (size_t)b * DA;
    float s = 0.f;
    #pragma unroll 4
    for (int i = 0; i < DA; i++)
        s = fmaf(a[i], Wemb[(size_t)i * EB + e], s);
    aW[(size_t)b * EB + e] = s;
}

__global__ void build_hs_k(const float* __restrict__ aW, const float* __restrict__ Wemb,
                           const float* __restrict__ bemb, const float* __restrict__ wpe,
                           float* __restrict__ Hs, bf16* __restrict__ Hh, bf16* __restrict__ Hl)
{
    int row = blockIdx.x;
    int n = row & (SEQ - 1), b = row >> 10;
    int e = threadIdx.x * 4;
    float4 w1 = *(const float4*)&Wemb[(size_t)651 * EB + e];
    float4 w2 = *(const float4*)&Wemb[(size_t)652 * EB + e];
    float4 bb = *(const float4*)&bemb[e];
    float4 pp = *(const float4*)&wpe[(size_t)n * EB + e];
    float pos = (float)(n + 1);
    float4 v;
    v.x = w1.x + pos * w2.x + bb.x + pp.x;
    v.y = w1.y + pos * w2.y + bb.y + pp.y;
    v.z = w1.z + pos * w2.z + bb.z + pp.z;
    v.w = w1.w + pos * w2.w + bb.w + pp.w;
    if (!(n & 1)) {
        float4 av = *(const float4*)&aW[(size_t)b * EB + e];
        v.x += av.x; v.y += av.y; v.z += av.z; v.w += av.w;
    }
    *(float4*)&Hs[(size_t)row * EB + e] = v;
    bf16 h, l;
    split1(v.x, h, l); Hh[(size_t)row * EB + e + 0] = h; Hl[(size_t)row * EB + e + 0] = l;
    split1(v.y, h, l); Hh[(size_t)row * EB + e + 1] = h; Hl[(size_t)row * EB + e + 1] = l;
    split1(v.z, h, l); Hh[(size_t)row * EB + e + 2] = h; Hl[(size_t)row * EB + e + 2] = l;
    split1(v.w, h, l); Hh[(size_t)row * EB + e + 3] = h; Hl[(size_t)row * EB + e + 3] = l;
}

// ---------------------------------------------------------------------------
// Prediction head
// ---------------------------------------------------------------------------
__global__ void pred_k(const float* __restrict__ Hs, const float* __restrict__ Wp,
                       const float* __restrict__ bp, float* __restrict__ out)
{
    int idx = blockIdx.x;
    int b = idx >> 9, h = idx & 511;
    const float* x = Hs + ((size_t)(b * SEQ + 2 * h)) * EB;
    int tid = threadIdx.x, lane = tid & 31, warp = tid >> 5;

    float4 xv = *(const float4*)&x[tid * 4];
    float xs[4] = { xv.x, xv.y, xv.z, xv.w };
    const float* w0 = Wp + (size_t)(tid * 4) * AD;

    float p[AD];
    #pragma unroll
    for (int ad = 0; ad < AD; ++ad) p[ad] = 0.f;
    #pragma unroll
    for (int t = 0; t < 4; t++)
        #pragma unroll
        for (int ad = 0; ad < AD; ++ad)
            p[ad] = fmaf(xs[t], w0[t * AD + ad], p[ad]);

    __shared__ float red[8][AD];
    #pragma unroll
    for (int ad = 0; ad < AD; ad++) {
        float s = p[ad];
        #pragma unroll
        for (int o = 16; o; o >>= 1) s += __shfl_down_sync(0xffffffffu, s, o);
        if (!lane) red[warp][ad] = s;
    }
    __syncthreads();
    if (tid < AD) {
        float s = 0.f;
        #pragma unroll
        for (int w = 0; w < 8; w++) s += red[w][tid];
        out[(size_t)idx * AD + tid] = s + bp[tid];
    }
}

// ---------------------------------------------------------------------------
extern "C" void kernel_launch(void* const* d_in, const int* in_sizes, int n_in,
                              void* d_out, int out_size)
{
    const float* action_set = (const float*)d_in[0];
    const float* wpe    = (const float*)d_in[2];
    const float* W_emb  = (const float*)d_in[3];
    const float* b_emb  = (const float*)d_in[4];
    const float* Wq     = (const float*)d_in[5];
    const float* Wk     = (const float*)d_in[6];
    const float* Wv     = (const float*)d_in[7];
    const float* ln1_g  = (const float*)d_in[8];
    const float* ln1_b  = (const float*)d_in[9];
    const float* W1     = (const float*)d_in[10];
    const float* b1     = (const float*)d_in[11];
    const float* W2     = (const float*)d_in[12];
    const float* b2     = (const float*)d_in[13];
    const float* ln2_g  = (const float*)d_in[14];
    const float* ln2_b  = (const float*)d_in[15];
    const float* W_pred = (const float*)d_in[16];
    const float* b_pred = (const float*)d_in[17];
    float* out = (float*)d_out;

    float *Hs, *T, *aW;
    cudaGetSymbolAddress((void**)&Hs, d_Hs);
    cudaGetSymbolAddress((void**)&T,  d_T);
    cudaGetSymbolAddress((void**)&aW, d_aW);
    bf16 *Hh, *Hl, *Qh, *Ql, *Kh, *Kl, *Vth, *Vtl, *Sh, *Sl;
    cudaGetSymbolAddress((void**)&Hh, d_Hh);   cudaGetSymbolAddress((void**)&Hl, d_Hl);
    cudaGetSymbolAddress((void**)&Qh, d_Qh);   cudaGetSymbolAddress((void**)&Ql, d_Ql);
    cudaGetSymbolAddress((void**)&Kh, d_Kh);   cudaGetSymbolAddress((void**)&Kl, d_Kl);
    cudaGetSymbolAddress((void**)&Vth, d_Vth); cudaGetSymbolAddress((void**)&Vtl, d_Vtl);
    cudaGetSymbolAddress((void**)&Sh, d_Sh);   cudaGetSymbolAddress((void**)&Sl, d_Sl);
    bf16 *Wqh, *Wql, *Wkh, *Wkl, *Wvh, *Wvl, *W1h, *W1l, *W2h, *W2l;
    cudaGetSymbolAddress((void**)&Wqh, d_Wq_h); cudaGetSymbolAddress((void**)&Wql, d_Wq_l);
    cudaGetSymbolAddress((void**)&Wkh, d_Wk_h); cudaGetSymbolAddress((void**)&Wkl, d_Wk_l);
    cudaGetSymbolAddress((void**)&Wvh, d_Wv_h); cudaGetSymbolAddress((void**)&Wvl, d_Wv_l);
    cudaGetSymbolAddress((void**)&W1h, d_W1_h); cudaGetSymbolAddress((void**)&W1l, d_W1_l);
    cudaGetSymbolAddress((void**)&W2h, d_W2_h); cudaGetSymbolAddress((void**)&W2l, d_W2_l);

    cudaFuncSetAttribute(gemm_k<EPI_SPLIT,    false>, cudaFuncAttributeMaxDynamicSharedMemorySize, SMB);
    cudaFuncSetAttribute(gemm_k<EPI_SC_SPLIT, false>, cudaFuncAttributeMaxDynamicSharedMemorySize, SMB);
    cudaFuncSetAttribute(gemm_k<EPI_NONE,     true >, cudaFuncAttributeMaxDynamicSharedMemorySize, SMB);
    cudaFuncSetAttribute(gemm_k<EPI_BR_SPLIT, false>, cudaFuncAttributeMaxDynamicSharedMemorySize, SMB);
    cudaFuncSetAttribute(gemm_k<EPI_BIAS,     false>, cudaFuncAttributeMaxDynamicSharedMemorySize, SMB);

    const dim3 cw(EB / 32, EB / 32, NLAY);
    const dim3 ct(32, 8);
    const dim3 gBig(EB / BN, MTOT / BM, 1);       // (8, 128)
    const dim3 gAtt(SEQ / BN, SEQ / BM, NBAT);    // (8, 8, 16)
    const dim3 gVt (SEQ / BN, EB / BM, NBAT);     // (8, 8, 16)
    const size_t sNE = (size_t)SEQ * EB;
    const size_t sSS = (size_t)SEQ * SEQ;
    const size_t sW  = (size_t)EB * EB;

    // embedding first, then the two convTs needed by Q/K, so the first big
    // GEMM sits at launch index ~4-5 where ncu's -s 5 -c 1 capture lands.
    aw_k<<<dim3(EB / 128, NBAT), 128>>>(action_set, W_emb, aW);          // 0
    build_hs_k<<<MTOT, 256>>>(aW, W_emb, b_emb, wpe, Hs, Hh, Hl);        // 1
    convT_k<<<cw, ct>>>(Wq, Wqh, Wql, EB, EB);                            // 2
    convT_k<<<cw, ct>>>(Wk, Wkh, Wkl, EB, EB);                            // 3

    for (int l = 0; l < NLAY; ++l) {
        const size_t lw = (size_t)l * sW;
        // Q = H Wq,  K = H Wk   (split outputs)
        gemm_k<EPI_SPLIT, false><<<gBig, 256, SMB>>>(Hh, Hl, Wqh + lw, Wql + lw,
            nullptr, nullptr, Qh, Ql, EB, EB, 0, 0, 0);                   // l=0: 4
        gemm_k<EPI_SPLIT, false><<<gBig, 256, SMB>>>(Hh, Hl, Wkh + lw, Wkl + lw,
            nullptr, nullptr, Kh, Kl, EB, EB, 0, 0, 0);                   // l=0: 5
        if (l == 0) {   // remaining weight converts, before first use
            convT_k<<<cw, ct>>>(Wv, Wvh, Wvl, EB, EB);
            convT_k<<<cw, ct>>>(W1, W1h, W1l, EB, EB);
            convT_k<<<cw, ct>>>(W2, W2h, W2l, EB, EB);
        }
        // V^T directly: Vt[e,s] = sum_k Wv[k,e] H[s,k]   (batched, split out)
        gemm_k<EPI_SPLIT, false><<<gVt, 256, SMB>>>(Wvh + lw, Wvl + lw, Hh, Hl,
            nullptr, nullptr, Vth, Vtl, SEQ, EB, 0, sNE, sNE);
        // S = relu(Q K^T) * mask  -> bf16 hi/lo (above-diagonal tiles skipped)
        gemm_k<EPI_SC_SPLIT, false><<<gAtt, 256, SMB>>>(Qh, Ql, Kh, Kl,
            nullptr, nullptr, Sh, Sl, SEQ, EB, sNE, sNE, sSS);
        // T = S V (triangular K-loop)
        gemm_k<EPI_NONE, true><<<gAtt, 256, SMB>>>(Sh, Sl, Vth, Vtl,
            nullptr, T, nullptr, nullptr, EB, SEQ, sSS, sNE, sNE);
        ln_k<<<MTOT, 256>>>(Hs, T, ln1_g + (size_t)l * EB, ln1_b + (size_t)l * EB, Hh, Hl);
        gemm_k<EPI_BR_SPLIT, false><<<gBig, 256, SMB>>>(Hh, Hl, W1h + lw, W1l + lw,
            b1 + (size_t)l * EB, nullptr, Sh, Sl, EB, EB, 0, 0, 0);
        gemm_k<EPI_BIAS, false><<<gBig, 256, SMB>>>(Sh, Sl, W2h + lw, W2l + lw,
            b2 + (size_t)l * EB, T, nullptr, nullptr, EB, EB, 0, 0, 0);
        ln_k<<<MTOT, 256>>>(Hs, T, ln2_g + (size_t)l * EB, ln2_b + (size_t)l * EB, Hh, Hl);
    }

    pred_k<<<NBAT * HORZ, 256>>>(Hs, W_pred, b_pred, out);
}

// round 10
// speedup vs baseline: 1.4791x; 1.4791x over previous
#include <cuda_runtime.h>
#include <cuda_bf16.h>
#include <cstdint>
#include <cstddef>

// Problem constants
constexpr int EB   = 1024;
constexpr int NBAT = 16;
constexpr int SEQ  = 1024;
constexpr int NLAY = 12;
constexpr int MTOT = NBAT * SEQ;   // 16384
constexpr int AD   = 10;
constexpr int DA   = 640;
constexpr int HORZ = 512;

typedef __nv_bfloat16 bf16;

// Does this compilation pass support arch-specific sm_103a instructions?
#if defined(__CUDA_ARCH__) && (defined(__CUDA_ARCH_FEAT_SM103_ALL) || \
    (defined(__CUDA_ARCH_SPECIFIC__)) || (defined(__CUDA_ARCH_FAMILY_SPECIFIC__)))
#define TC_OK 1
#else
#define TC_OK 0
#endif

// ---------------- scratch (device globals; no allocations allowed) ----------
__device__ float d_Hs[(size_t)MTOT * EB];
__device__ float d_T [(size_t)MTOT * EB];
__device__ float d_aW[(size_t)NBAT * EB];

__device__ bf16 d_Hh[(size_t)MTOT * EB],  d_Hl[(size_t)MTOT * EB];
__device__ bf16 d_Qh[(size_t)MTOT * EB],  d_Ql[(size_t)MTOT * EB];
__device__ bf16 d_Kh[(size_t)MTOT * EB],  d_Kl[(size_t)MTOT * EB];
__device__ bf16 d_Vth[(size_t)MTOT * EB], d_Vtl[(size_t)MTOT * EB];
__device__ bf16 d_Sh[(size_t)NBAT * SEQ * SEQ], d_Sl[(size_t)NBAT * SEQ * SEQ];
__device__ bf16 d_Wq_h[(size_t)NLAY * EB * EB], d_Wq_l[(size_t)NLAY * EB * EB];
__device__ bf16 d_Wk_h[(size_t)NLAY * EB * EB], d_Wk_l[(size_t)NLAY * EB * EB];
__device__ bf16 d_Wv_h[(size_t)NLAY * EB * EB], d_Wv_l[(size_t)NLAY * EB * EB];
__device__ bf16 d_W1_h[(size_t)NLAY * EB * EB], d_W1_l[(size_t)NLAY * EB * EB];
__device__ bf16 d_W2_h[(size_t)NLAY * EB * EB], d_W2_l[(size_t)NLAY * EB * EB];

// ---------------- common helpers --------------------------------------------
__device__ __forceinline__ uint32_t cvs(const void* p) {
    return (uint32_t)__cvta_generic_to_shared(p);
}
__device__ __forceinline__ void split1(float x, bf16& h, bf16& l) {
    h = __float2bfloat16(x);
    l = __float2bfloat16(x - __bfloat162float(h));
}
#define CPA(dst, src) asm volatile("cp.async.cg.shared.global [%0],[%1],16;\n" :: "r"(dst), "l"(src))
#define CP_COMMIT()   asm volatile("cp.async.commit_group;\n")
#define CP_WAIT0()    asm volatile("cp.async.wait_group 0;\n")
#define CP_WAIT1()    asm volatile("cp.async.wait_group 1;\n")

// legacy mma.sync helpers (valid on all passes)
__device__ __forceinline__ void ldsm4(uint32_t* r, uint32_t addr) {
    asm volatile("ldmatrix.sync.aligned.m8n8.x4.shared.b16 {%0,%1,%2,%3},[%4];"
                 : "=r"(r[0]), "=r"(r[1]), "=r"(r[2]), "=r"(r[3]) : "r"(addr));
}
__device__ __forceinline__ void mma16816(float* d, const uint32_t* a,
                                         uint32_t b0, uint32_t b1) {
    asm volatile("mma.sync.aligned.m16n8k16.row.col.f32.bf16.bf16.f32 "
                 "{%0,%1,%2,%3},{%4,%5,%6,%7},{%8,%9},{%0,%1,%2,%3};"
                 : "+f"(d[0]), "+f"(d[1]), "+f"(d[2]), "+f"(d[3])
                 : "r"(a[0]), "r"(a[1]), "r"(a[2]), "r"(a[3]), "r"(b0), "r"(b1));
}

#if TC_OK
// ---------------- tcgen05 helpers (sm_103a-specific pass only) --------------
__device__ __forceinline__ uint32_t elect1() {
    uint32_t pred;
    asm volatile("{\n\t.reg .pred p;\n\telect.sync _|p, 0xFFFFFFFF;\n\t"
                 "selp.b32 %0, 1, 0, p;\n\t}" : "=r"(pred));
    return pred;
}
__device__ __forceinline__ uint64_t mk_desc(uint32_t base_addr) {
    constexpr uint64_t BASE =
        (uint64_t(2) << 61) | (uint64_t(1) << 46) | (uint64_t(64) << 32) | (uint64_t(1) << 16);
    return BASE | ((uint64_t)(base_addr >> 4) & 0x3FFF);
}
__device__ __forceinline__ void mma_f16_ss(uint32_t d, uint64_t ad, uint64_t bd,
                                           uint32_t idesc, uint32_t en) {
    asm volatile(
        "{\n\t.reg .pred p;\n\tsetp.ne.u32 p, %5, 0;\n\t"
        "tcgen05.mma.cta_group::1.kind::f16 [%0], %1, %2, %3, {%4,%4,%4,%4}, p;\n\t}"
        :: "r"(d), "l"(ad), "l"(bd), "r"(idesc), "r"(0u), "r"(en) : "memory");
}
__device__ __forceinline__ void tc_commit(uint32_t mbar) {
    asm volatile("tcgen05.commit.cta_group::1.mbarrier::arrive::one.shared::cluster.b64 [%0];"
                 :: "r"(mbar) : "memory");
}
__device__ __forceinline__ void mbar_init(uint32_t a, uint32_t cnt) {
    asm volatile("mbarrier.init.shared.b64 [%0], %1;" :: "r"(a), "r"(cnt) : "memory");
}
__device__ __forceinline__ void mbar_wait(uint32_t a, uint32_t parity) {
    asm volatile(
        "{\n\t.reg .pred P;\n\tW%=:\n\t"
        "mbarrier.try_wait.parity.acquire.cta.shared::cta.b64 P, [%0], %1, 0x989680;\n\t"
        "@!P bra W%=;\n\t}" :: "r"(a), "r"(parity) : "memory");
}
__device__ __forceinline__ void ld_tm32(uint32_t* r, uint32_t addr) {
    asm volatile(
        "tcgen05.ld.sync.aligned.32x32b.x32.b32 "
        "{%0,%1,%2,%3,%4,%5,%6,%7,%8,%9,%10,%11,%12,%13,%14,%15,"
        "%16,%17,%18,%19,%20,%21,%22,%23,%24,%25,%26,%27,%28,%29,%30,%31},[%32];"
        : "=r"(r[0]), "=r"(r[1]), "=r"(r[2]), "=r"(r[3]), "=r"(r[4]), "=r"(r[5]),
          "=r"(r[6]), "=r"(r[7]), "=r"(r[8]), "=r"(r[9]), "=r"(r[10]), "=r"(r[11]),
          "=r"(r[12]), "=r"(r[13]), "=r"(r[14]), "=r"(r[15]), "=r"(r[16]), "=r"(r[17]),
          "=r"(r[18]), "=r"(r[19]), "=r"(r[20]), "=r"(r[21]), "=r"(r[22]), "=r"(r[23]),
          "=r"(r[24]), "=r"(r[25]), "=r"(r[26]), "=r"(r[27]), "=r"(r[28]), "=r"(r[29]),
          "=r"(r[30]), "=r"(r[31])
        : "r"(addr));
}
#define TC_WAIT_LD()     asm volatile("tcgen05.wait::ld.sync.aligned;" ::: "memory")
#define TC_FENCE_AFTER() asm volatile("tcgen05.fence::after_thread_sync;" ::: "memory")
#define FENCE_ASYNC()    asm volatile("fence.proxy.async.shared::cta;" ::: "memory")
#endif  // TC_OK

// ---------------------------------------------------------------------------
// GEMM: C[M,N] = (Ah+Al)[M,K] @ (Bh+Bl)[N,K]^T  (3-term bf16x3, fp32 acc)
// tcgen05 path: CTA tile 128x128, BK=64 (SW128 rows), 3-stage cp.async
// (wait_group + syncthreads pipeline — round-7 proven), COALESCED loader:
// 8 consecutive lanes cover one contiguous 128B row -> 4 L1tex wavefronts
// per warp-instruction instead of 32.
// fallback path: mma.sync m16n8k16 (compile-only; tcgen05 wins fatbin dispatch)
// ---------------------------------------------------------------------------
constexpr int BM = 128, BN = 128;

// tcgen05 layout
constexpr int TC_BK   = 64;
constexpr int TC_PL   = BM * 128;           // plane bytes = 16384
constexpr int TC_STG  = 4 * TC_PL;          // stage bytes = 65536
constexpr int TC_HDR  = 1024;
constexpr int TC_NSTG = 3;
constexpr uint32_t IDESC =
    (1u << 4) | (1u << 7) | (1u << 10) | ((BN / 8) << 17) | ((BM / 16) << 24);
constexpr int TMEM_COLS_ALLOC = 128;

// fallback layout
constexpr int FB_BK  = 32;
constexpr int FB_PL  = BM * 40 * 2;       // 10240
constexpr int FB_STG = 4 * FB_PL;         // 40960
constexpr int FB_STAGES = 3;

constexpr int SMB = 1024 + TC_HDR + TC_NSTG * TC_STG;   // 198656

enum { EPI_NONE = 0, EPI_BIAS = 1, EPI_SPLIT = 2, EPI_BR_SPLIT = 3, EPI_SC_SPLIT = 4 };

#if TC_OK
// Coalesced stage loader: per plane, 1024 16B-chunks; thread t takes chunks
// {t, t+256, t+512, t+768}. Consecutive lanes -> consecutive 16B of the SAME
// 128B global row (8 lanes per row), so each warp cp.async touches only 4
// distinct 128B lines.
__device__ __forceinline__ void tc_load_stage(uint32_t stgBase,
    const bf16* __restrict__ Ah, const bf16* __restrict__ Al,
    const bf16* __restrict__ Bh, const bf16* __restrict__ Bl,
    int K, int k0, int row0, int col0, int tid)
{
    #pragma unroll
    for (int i = 0; i < 4; i++) {
        const int g   = i * 256 + tid;        // 0..1023
        const int row = g >> 3;               // 0..127
        const int c   = g & 7;                // 16B chunk within 128B row
        uint32_t off = (uint32_t)row * 128 + c * 16;
        uint32_t sw  = off ^ ((off >> 3) & 0x70);
        const size_t gA = (size_t)(row0 + row) * K + k0 + c * 8;
        const size_t gB = (size_t)(col0 + row) * K + k0 + c * 8;
        CPA(stgBase + 0 * TC_PL + sw, Ah + gA);
        CPA(stgBase + 1 * TC_PL + sw, Al + gA);
        CPA(stgBase + 2 * TC_PL + sw, Bh + gB);
        CPA(stgBase + 3 * TC_PL + sw, Bl + gB);
    }
}
#endif

__device__ __forceinline__ void fb_load_stage(uint32_t smBase,
    const bf16* __restrict__ Agh, const bf16* __restrict__ Agl,
    const bf16* __restrict__ Bgh, const bf16* __restrict__ Bgl,
    int K, int k0, int row0, int col0, int tid)
{
    const int row = tid >> 1;
    const int half = tid & 1;
    const uint32_t sm = smBase + row * 80 + half * 32;
    const size_t gA = (size_t)(row0 + row) * K + k0 + half * 16;
    const size_t gB = (size_t)(col0 + row) * K + k0 + half * 16;
    CPA(sm,                  Agh + gA); CPA(sm + 16,                  Agh + gA + 8);
    CPA(sm + FB_PL,          Agl + gA); CPA(sm + FB_PL + 16,          Agl + gA + 8);
    CPA(sm + 2 * FB_PL,      Bgh + gB); CPA(sm + 2 * FB_PL + 16,      Bgh + gB + 8);
    CPA(sm + 3 * FB_PL,      Bgl + gB); CPA(sm + 3 * FB_PL + 16,      Bgl + gB + 8);
}

template<int EPI, bool KLIM>
__global__ void __launch_bounds__(256, 1)
gemm_k(const bf16* __restrict__ Agh, const bf16* __restrict__ Agl,
       const bf16* __restrict__ Bgh, const bf16* __restrict__ Bgl,
       const float* __restrict__ bias,
       float* __restrict__ Cg, bf16* __restrict__ Chg, bf16* __restrict__ Clg,
       int N, int K, size_t sA, size_t sB, size_t sC)
{
    extern __shared__ char smem[];

    const int bx = blockIdx.x, by = blockIdx.y, bz = blockIdx.z;
    const int tid = threadIdx.x;
    const int lane = tid & 31, wid = tid >> 5;
    const int row0 = by * BM, col0 = bx * BN;

    // Score tiles strictly above the causal diagonal are NEVER read by the
    // S@V GEMM (its K-loop is clamped to (by+1)*BM), so skip entirely.
    if (EPI == EPI_SC_SPLIT && col0 >= row0 + BM) return;

    const bf16* Ah = Agh + (size_t)bz * sA;
    const bf16* Al = Agl + (size_t)bz * sA;
    const bf16* Bh = Bgh + (size_t)bz * sB;
    const bf16* Bl = Bgl + (size_t)bz * sB;

    int Keff = K;
    if (KLIM) { int km = (by + 1) * BM; Keff = km < K ? km : K; }

#if TC_OK
    // ======================= tcgen05 body ====================================
    const uint32_t sbRaw = cvs(smem);
    const uint32_t sb = (sbRaw + 1023u) & ~1023u;
    const uint32_t mDone = sb + 8;   // 3 done-mbarriers

    if (wid == 0)
        asm volatile("tcgen05.alloc.cta_group::1.sync.aligned.shared::cta.b32 [%0], %1;"
                     :: "r"(sb), "r"((uint32_t)TMEM_COLS_ALLOC) : "memory");
    if (tid == 0) { mbar_init(mDone + 0, 1); mbar_init(mDone + 8, 1); mbar_init(mDone + 16, 1); }
    __syncthreads();
    uint32_t tbase;
    asm volatile("ld.shared.b32 %0, [%1];" : "=r"(tbase) : "r"(sb));
    if (wid == 0)
        asm volatile("tcgen05.relinquish_alloc_permit.cta_group::1.sync.aligned;");

    const int NT = Keff / TC_BK;   // always >= 2 for our shapes

    // prologue: stages 0 and 1
    tc_load_stage(sb + TC_HDR,          Ah, Al, Bh, Bl, K, 0,     row0, col0, tid);
    CP_COMMIT();
    tc_load_stage(sb + TC_HDR + TC_STG, Ah, Al, Bh, Bl, K, TC_BK, row0, col0, tid);
    CP_COMMIT();

    int phm = 0;   // per-buffer done-phase bits

    for (int t = 0; t < NT; t++) {
        const int b = t % TC_NSTG;
        if (t + 1 < NT) { CP_WAIT1(); } else { CP_WAIT0(); }
        FENCE_ASYNC();
        __syncthreads();

        if (wid == 0) {
            TC_FENCE_AFTER();
            if (elect1()) {
                const uint32_t stg = sb + TC_HDR + b * TC_STG;
                const uint64_t adh = mk_desc(stg);
                const uint64_t adl = mk_desc(stg + TC_PL);
                const uint64_t bdh = mk_desc(stg + 2 * TC_PL);
                const uint64_t bdl = mk_desc(stg + 3 * TC_PL);
                #pragma unroll
                for (int ks = 0; ks < 4; ks++) {
                    uint32_t en0 = (t > 0 || ks > 0) ? 1u : 0u;
                    mma_f16_ss(tbase, adh + ks * 2, bdh + ks * 2, IDESC, en0);
                    mma_f16_ss(tbase, adh + ks * 2, bdl + ks * 2, IDESC, 1u);
                    mma_f16_ss(tbase, adl + ks * 2, bdh + ks * 2, IDESC, 1u);
                }
                tc_commit(mDone + b * 8);
            }
        }

        if (t + 2 < NT) {
            const int nb = (t + 2) % TC_NSTG;
            if (t >= 1) {   // buffer nb was used by MMA tile t-1: wait completion
                mbar_wait(mDone + nb * 8, (phm >> nb) & 1);
                phm ^= (1 << nb);
            }
            tc_load_stage(sb + TC_HDR + nb * TC_STG, Ah, Al, Bh, Bl, K,
                          (t + 2) * TC_BK, row0, col0, tid);
            CP_COMMIT();
        }
    }

    // final MMA completion (commit tracks all prior MMAs)
    const int lb = (NT - 1) % TC_NSTG;
    mbar_wait(mDone + lb * 8, (phm >> lb) & 1);
    TC_FENCE_AFTER();

    // epilogue: warp w -> rows (w&3)*32+lane, cols (w>>2)*64 .. +63
    {
        const int wq = wid & 3;
        const int colh = (wid >> 2) * 64;
        const uint32_t toff = tbase + ((uint32_t)wq << 21) + (uint32_t)colh;
        const int r = row0 + wq * 32 + lane;

        uint32_t dr[64];
        ld_tm32(dr,      toff);
        ld_tm32(dr + 32, toff + 32);
        TC_WAIT_LD();

        const int cbase = col0 + colh;
        if (EPI == EPI_NONE || EPI == EPI_BIAS) {
            float* C = Cg + (size_t)bz * sC + (size_t)r * N + cbase;
            #pragma unroll
            for (int j = 0; j < 64; j += 4) {
                float4 v;
                v.x = __uint_as_float(dr[j + 0]);
                v.y = __uint_as_float(dr[j + 1]);
                v.z = __uint_as_float(dr[j + 2]);
                v.w = __uint_as_float(dr[j + 3]);
                if (EPI == EPI_BIAS) {
                    v.x += bias[cbase + j];     v.y += bias[cbase + j + 1];
                    v.z += bias[cbase + j + 2]; v.w += bias[cbase + j + 3];
                }
                *(float4*)&C[j] = v;
            }
        } else {
            bf16* Ch = Chg + (size_t)bz * sC + (size_t)r * N + cbase;
            bf16* Cl = Clg + (size_t)bz * sC + (size_t)r * N + cbase;
            float inv = (EPI == EPI_SC_SPLIT) ? 1.0f / (float)(r + 1) : 0.f;
            #pragma unroll
            for (int j = 0; j < 64; j += 2) {
                float x0 = __uint_as_float(dr[j]);
                float x1 = __uint_as_float(dr[j + 1]);
                if (EPI == EPI_BR_SPLIT) {
                    x0 = fmaxf(x0 + bias[cbase + j], 0.f);
                    x1 = fmaxf(x1 + bias[cbase + j + 1], 0.f);
                } else if (EPI == EPI_SC_SPLIT) {
                    x0 = (cbase + j     <= r) ? fmaxf(x0, 0.f) * inv : 0.f;
                    x1 = (cbase + j + 1 <= r) ? fmaxf(x1, 0.f) * inv : 0.f;
                }
                bf16 h0, l0, h1, l1;
                split1(x0, h0, l0); split1(x1, h1, l1);
                __nv_bfloat162 vh; vh.x = h0; vh.y = h1;
                __nv_bfloat162 vl; vl.x = l0; vl.y = l1;
                *(__nv_bfloat162*)&Ch[j] = vh;
                *(__nv_bfloat162*)&Cl[j] = vl;
            }
        }
    }

    __syncthreads();
    if (wid == 0)
        asm volatile("tcgen05.dealloc.cta_group::1.sync.aligned.b32 %0, %1;"
                     :: "r"(tbase), "r"((uint32_t)TMEM_COLS_ALLOC));

#else
    // ======================= mma.sync fallback body ==========================
    const uint32_t smBase = cvs(smem);
    const int NT = Keff / FB_BK;

    float acc[2][8][4];
    #pragma unroll
    for (int i = 0; i < 2; i++)
        #pragma unroll
        for (int j = 0; j < 8; j++)
            #pragma unroll
            for (int q = 0; q < 4; q++) acc[i][j][q] = 0.f;

    const int wm = wid >> 1, wn = wid & 1;
    const int lr = lane & 15;
    const uint32_t colo = (uint32_t)(lane >> 4) * 16;

    #pragma unroll
    for (int s = 0; s < FB_STAGES - 1; s++) {
        if (s < NT) fb_load_stage(smBase + s * FB_STG, Ah, Al, Bh, Bl, K, s * FB_BK, row0, col0, tid);
        CP_COMMIT();
    }

    for (int t = 0; t < NT; t++) {
        CP_WAIT1();
        __syncthreads();

        int tp = t + FB_STAGES - 1;
        if (tp < NT)
            fb_load_stage(smBase + (tp % FB_STAGES) * FB_STG, Ah, Al, Bh, Bl, K, tp * FB_BK, row0, col0, tid);
        CP_COMMIT();

        const uint32_t stg = smBase + (t % FB_STAGES) * FB_STG;
        const uint32_t aRow = stg + (uint32_t)(wm * 32 + lr) * 80 + colo;
        const uint32_t bRow = stg + 2 * FB_PL + (uint32_t)(wn * 64 + lr) * 80 + colo;

        #pragma unroll
        for (int kk = 0; kk < 2; kk++) {
            const uint32_t ka = aRow + kk * 32, kb = bRow + kk * 32;
            uint32_t ah[2][4], al[2][4];
            #pragma unroll
            for (int mf = 0; mf < 2; mf++) {
                ldsm4(ah[mf], ka + mf * 16 * 80);
                ldsm4(al[mf], ka + FB_PL + mf * 16 * 80);
            }
            uint32_t bh[4][4], blf[4][4];
            #pragma unroll
            for (int g = 0; g < 4; g++) {
                ldsm4(bh[g], kb + g * 16 * 80);
                ldsm4(blf[g], kb + FB_PL + g * 16 * 80);
            }
            #pragma unroll
            for (int mf = 0; mf < 2; mf++) {
                #pragma unroll
                for (int g = 0; g < 4; g++) {
                    mma16816(acc[mf][2 * g],     ah[mf], bh[g][0],  bh[g][2]);
                    mma16816(acc[mf][2 * g],     ah[mf], blf[g][0], blf[g][2]);
                    mma16816(acc[mf][2 * g],     al[mf], bh[g][0],  bh[g][2]);
                    mma16816(acc[mf][2 * g + 1], ah[mf], bh[g][1],  bh[g][3]);
                    mma16816(acc[mf][2 * g + 1], ah[mf], blf[g][1], blf[g][3]);
                    mma16816(acc[mf][2 * g + 1], al[mf], bh[g][1],  bh[g][3]);
                }
            }
        }
        __syncthreads();
    }
    CP_WAIT0();

    float*  C  = (EPI == EPI_NONE || EPI == EPI_BIAS) ? Cg + (size_t)bz * sC : nullptr;
    bf16*   Ch = (EPI >= EPI_SPLIT) ? Chg + (size_t)bz * sC : nullptr;
    bf16*   Cl = (EPI >= EPI_SPLIT) ? Clg + (size_t)bz * sC : nullptr;
    const int qr = lane >> 2, qc = (lane & 3) * 2;
    #pragma unroll
    for (int mf = 0; mf < 2; mf++) {
        #pragma unroll
        for (int nf = 0; nf < 8; nf++) {
            int rA = row0 + wm * 32 + mf * 16 + qr;
            int cb = col0 + wn * 64 + nf * 8 + qc;
            #pragma unroll
            for (int half = 0; half < 2; half++) {
                int r = rA + half * 8;
                float x0 = acc[mf][nf][half * 2 + 0];
                float x1 = acc[mf][nf][half * 2 + 1];
                if (EPI == EPI_BIAS) {
                    x0 += bias[cb]; x1 += bias[cb + 1];
                } else if (EPI == EPI_BR_SPLIT) {
                    x0 = fmaxf(x0 + bias[cb], 0.f);
                    x1 = fmaxf(x1 + bias[cb + 1], 0.f);
                } else if (EPI == EPI_SC_SPLIT) {
                    float inv = 1.0f / (float)(r + 1);
                    x0 = (cb     <= r) ? fmaxf(x0, 0.f) * inv : 0.f;
                    x1 = (cb + 1 <= r) ? fmaxf(x1, 0.f) * inv : 0.f;
                }
                if (EPI == EPI_NONE || EPI == EPI_BIAS) {
                    float2 v; v.x = x0; v.y = x1;
                    *(float2*)&C[(size_t)r * N + cb] = v;
                } else {
                    bf16 h0, l0, h1, l1;
                    split1(x0, h0, l0); split1(x1, h1, l1);
                    __nv_bfloat162 vh; vh.x = h0; vh.y = h1;
                    __nv_bfloat162 vl; vl.x = l0; vl.y = l1;
                    *(__nv_bfloat162*)&Ch[(size_t)r * N + cb] = vh;
                    *(__nv_bfloat162*)&Cl[(size_t)r * N + cb] = vl;
                }
            }
        }
    }
#endif
}

// ---------------------------------------------------------------------------
// Transpose + split-convert: in[z][R][C] fp32 -> oh/ol[z][C][R] bf16
// (weights only, once per launch)
// ---------------------------------------------------------------------------
__global__ void convT_k(const float* __restrict__ in, bf16* __restrict__ oh,
                        bf16* __restrict__ ol, int R, int C)
{
    const int z = blockIdx.z;
    in += (size_t)z * R * C;
    oh += (size_t)z * R * C;
    ol += (size_t)z * R * C;
    __shared__ float t[32][33];
    const int c0 = blockIdx.x * 32, r0 = blockIdx.y * 32;
    const int tx = threadIdx.x, ty = threadIdx.y;
    #pragma unroll
    for (int i = 0; i < 4; i++)
        t[ty + i * 8][tx] = in[(size_t)(r0 + ty + i * 8) * C + c0 + tx];
    __syncthreads();
    #pragma unroll
    for (int i = 0; i < 4; i++) {
        float v = t[tx][ty + i * 8];
        int cc = c0 + ty + i * 8, rr = r0 + tx;
        bf16 h, l; split1(v, h, l);
        oh[(size_t)cc * R + rr] = h;
        ol[(size_t)cc * R + rr] = l;
    }
}

// ---------------------------------------------------------------------------
// Fused residual + LayerNorm, emitting fp32 + bf16 hi/lo
// ---------------------------------------------------------------------------
__global__ void ln_k(float* __restrict__ Hs, const float* __restrict__ Res,
                     const float* __restrict__ g, const float* __restrict__ be,
                     bf16* __restrict__ Hh, bf16* __restrict__ Hl)
{
    int row = blockIdx.x;
    int tid = threadIdx.x;
    int lane = tid & 31, warp = tid >> 5;
    __shared__ float sm[8];

    float4 x = *(float4*)&Hs[(size_t)row * EB + tid * 4];
    float4 rr = *(const float4*)&Res[(size_t)row * EB + tid * 4];
    x.x += rr.x; x.y += rr.y; x.z += rr.z; x.w += rr.w;

    float s = x.x + x.y + x.z + x.w;
    #pragma unroll
    for (int o = 16; o; o >>= 1) s += __shfl_down_sync(0xffffffffu, s, o);
    if (!lane) sm[warp] = s;
    __syncthreads();
    float mu;
    {
        float t = (lane < 8) ? sm[lane] : 0.f;
        #pragma unroll
        for (int o = 4; o; o >>= 1) t += __shfl_down_sync(0xffffffffu, t, o);
        mu = __shfl_sync(0xffffffffu, t, 0) * (1.0f / 1024.0f);
    }
    __syncthreads();

    float dx0 = x.x - mu, dx1 = x.y - mu, dx2 = x.z - mu, dx3 = x.w - mu;
    float sq = dx0 * dx0 + dx1 * dx1 + dx2 * dx2 + dx3 * dx3;
    #pragma unroll
    for (int o = 16; o; o >>= 1) sq += __shfl_down_sync(0xffffffffu, sq, o);
    if (!lane) sm[warp] = sq;
    __syncthreads();
    float rstd;
    {
        float t = (lane < 8) ? sm[lane] : 0.f;
        #pragma unroll
        for (int o = 4; o; o >>= 1) t += __shfl_down_sync(0xffffffffu, t, o);
        float var = __shfl_sync(0xffffffffu, t, 0) * (1.0f / 1024.0f);
        rstd = rsqrtf(var + 1e-5f);
    }

    float4 gv = *(const float4*)&g[tid * 4];
    float4 bv = *(const float4*)&be[tid * 4];
    float4 o;
    o.x = dx0 * rstd * gv.x + bv.x;
    o.y = dx1 * rstd * gv.y + bv.y;
    o.z = dx2 * rstd * gv.z + bv.z;
    o.w = dx3 * rstd * gv.w + bv.w;
    *(float4*)&Hs[(size_t)row * EB + tid * 4] = o;

    bf16 h0, l0, h1, l1, h2, l2, h3, l3;
    split1(o.x, h0, l0); split1(o.y, h1, l1);
    split1(o.z, h2, l2); split1(o.w, h3, l3);
    __nv_bfloat162 a0; a0.x = h0; a0.y = h1;
    __nv_bfloat162 a1; a1.x = h2; a1.y = h3;
    __nv_bfloat162 b0; b0.x = l0; b0.y = l1;
    __nv_bfloat162 b1; b1.x = l2; b1.y = l3;
    *(__nv_bfloat162*)&Hh[(size_t)row * EB + tid * 4]     = a0;
    *(__nv_bfloat162*)&Hh[(size_t)row * EB + tid * 4 + 2] = a1;
    *(__nv_bfloat162*)&Hl[(size_t)row * EB + tid * 4]     = b0;
    *(__nv_bfloat162*)&Hl[(size_t)row * EB + tid * 4 + 2] = b1;
}

// ---------------------------------------------------------------------------
// Embedding
// ---------------------------------------------------------------------------
__global__ void aw_k(const float* __restrict__ act, const float* __restrict__ Wemb,
                     float* __restrict__ aW)
{
    int e = blockIdx.x * 128 + threadIdx.x;
    int b = blockIdx.y;
    const float* a = act + (size_t)b * DA;
    float s = 0.f;
    #pragma unroll 4
    for (int i = 0; i < DA; i++)
        s = fmaf(a[i], Wemb[(size_t)i * EB + e], s);
    aW[(size_t)b * EB + e] = s;
}

__global__ void build_hs_k(const float* __restrict__ aW, const float* __restrict__ Wemb,
                           const float* __restrict__ bemb, const float* __restrict__ wpe,
                           float* __restrict__ Hs, bf16* __restrict__ Hh, bf16* __restrict__ Hl)
{
    int row = blockIdx.x;
    int n = row & (SEQ - 1), b = row >> 10;
    int e = threadIdx.x * 4;
    float4 w1 = *(const float4*)&Wemb[(size_t)651 * EB + e];
    float4 w2 = *(const float4*)&Wemb[(size_t)652 * EB + e];
    float4 bb = *(const float4*)&bemb[e];
    float4 pp = *(const float4*)&wpe[(size_t)n * EB + e];
    float pos = (float)(n + 1);
    float4 v;
    v.x = w1.x + pos * w2.x + bb.x + pp.x;
    v.y = w1.y + pos * w2.y + bb.y + pp.y;
    v.z = w1.z + pos * w2.z + bb.z + pp.z;
    v.w = w1.w + pos * w2.w + bb.w + pp.w;
    if (!(n & 1)) {
        float4 av = *(const float4*)&aW[(size_t)b * EB + e];
        v.x += av.x; v.y += av.y; v.z += av.z; v.w += av.w;
    }
    *(float4*)&Hs[(size_t)row * EB + e] = v;
    bf16 h, l;
    split1(v.x, h, l); Hh[(size_t)row * EB + e + 0] = h; Hl[(size_t)row * EB + e + 0] = l;
    split1(v.y, h, l); Hh[(size_t)row * EB + e + 1] = h; Hl[(size_t)row * EB + e + 1] = l;
    split1(v.z, h, l); Hh[(size_t)row * EB + e + 2] = h; Hl[(size_t)row * EB + e + 2] = l;
    split1(v.w, h, l); Hh[(size_t)row * EB + e + 3] = h; Hl[(size_t)row * EB + e + 3] = l;
}

// ---------------------------------------------------------------------------
// Prediction head
// ---------------------------------------------------------------------------
__global__ void pred_k(const float* __restrict__ Hs, const float* __restrict__ Wp,
                       const float* __restrict__ bp, float* __restrict__ out)
{
    int idx = blockIdx.x;
    int b = idx >> 9, h = idx & 511;
    const float* x = Hs + ((size_t)(b * SEQ + 2 * h)) * EB;
    int tid = threadIdx.x, lane = tid & 31, warp = tid >> 5;

    float4 xv = *(const float4*)&x[tid * 4];
    float xs[4] = { xv.x, xv.y, xv.z, xv.w };
    const float* w0 = Wp + (size_t)(tid * 4) * AD;

    float p[AD];
    #pragma unroll
    for (int ad = 0; ad < AD; ++ad) p[ad] = 0.f;
    #pragma unroll
    for (int t = 0; t < 4; t++)
        #pragma unroll
        for (int ad = 0; ad < AD; ++ad)
            p[ad] = fmaf(xs[t], w0[t * AD + ad], p[ad]);

    __shared__ float red[8][AD];
    #pragma unroll
    for (int ad = 0; ad < AD; ad++) {
        float s = p[ad];
        #pragma unroll
        for (int o = 16; o; o >>= 1) s += __shfl_down_sync(0xffffffffu, s, o);
        if (!lane) red[warp][ad] = s;
    }
    __syncthreads();
    if (tid < AD) {
        float s = 0.f;
        #pragma unroll
        for (int w = 0; w < 8; w++) s += red[w][tid];
        out[(size_t)idx * AD + tid] = s + bp[tid];
    }
}

// ---------------------------------------------------------------------------
extern "C" void kernel_launch(void* const* d_in, const int* in_sizes, int n_in,
                              void* d_out, int out_size)
{
    const float* action_set = (const float*)d_in[0];
    const float* wpe    = (const float*)d_in[2];
    const float* W_emb  = (const float*)d_in[3];
    const float* b_emb  = (const float*)d_in[4];
    const float* Wq     = (const float*)d_in[5];
    const float* Wk     = (const float*)d_in[6];
    const float* Wv     = (const float*)d_in[7];
    const float* ln1_g  = (const float*)d_in[8];
    const float* ln1_b  = (const float*)d_in[9];
    const float* W1     = (const float*)d_in[10];
    const float* b1     = (const float*)d_in[11];
    const float* W2     = (const float*)d_in[12];
    const float* b2     = (const float*)d_in[13];
    const float* ln2_g  = (const float*)d_in[14];
    const float* ln2_b  = (const float*)d_in[15];
    const float* W_pred = (const float*)d_in[16];
    const float* b_pred = (const float*)d_in[17];
    float* out = (float*)d_out;

    float *Hs, *T, *aW;
    cudaGetSymbolAddress((void**)&Hs, d_Hs);
    cudaGetSymbolAddress((void**)&T,  d_T);
    cudaGetSymbolAddress((void**)&aW, d_aW);
    bf16 *Hh, *Hl, *Qh, *Ql, *Kh, *Kl, *Vth, *Vtl, *Sh, *Sl;
    cudaGetSymbolAddress((void**)&Hh, d_Hh);   cudaGetSymbolAddress((void**)&Hl, d_Hl);
    cudaGetSymbolAddress((void**)&Qh, d_Qh);   cudaGetSymbolAddress((void**)&Ql, d_Ql);
    cudaGetSymbolAddress((void**)&Kh, d_Kh);   cudaGetSymbolAddress((void**)&Kl, d_Kl);
    cudaGetSymbolAddress((void**)&Vth, d_Vth); cudaGetSymbolAddress((void**)&Vtl, d_Vtl);
    cudaGetSymbolAddress((void**)&Sh, d_Sh);   cudaGetSymbolAddress((void**)&Sl, d_Sl);
    bf16 *Wqh, *Wql, *Wkh, *Wkl, *Wvh, *Wvl, *W1h, *W1l, *W2h, *W2l;
    cudaGetSymbolAddress((void**)&Wqh, d_Wq_h); cudaGetSymbolAddress((void**)&Wql, d_Wq_l);
    cudaGetSymbolAddress((void**)&Wkh, d_Wk_h); cudaGetSymbolAddress((void**)&Wkl, d_Wk_l);
    cudaGetSymbolAddress((void**)&Wvh, d_Wv_h); cudaGetSymbolAddress((void**)&Wvl, d_Wv_l);
    cudaGetSymbolAddress((void**)&W1h, d_W1_h); cudaGetSymbolAddress((void**)&W1l, d_W1_l);
    cudaGetSymbolAddress((void**)&W2h, d_W2_h); cudaGetSymbolAddress((void**)&W2l, d_W2_l);

    cudaFuncSetAttribute(gemm_k<EPI_SPLIT,    false>, cudaFuncAttributeMaxDynamicSharedMemorySize, SMB);
    cudaFuncSetAttribute(gemm_k<EPI_SC_SPLIT, false>, cudaFuncAttributeMaxDynamicSharedMemorySize, SMB);
    cudaFuncSetAttribute(gemm_k<EPI_NONE,     true >, cudaFuncAttributeMaxDynamicSharedMemorySize, SMB);
    cudaFuncSetAttribute(gemm_k<EPI_BR_SPLIT, false>, cudaFuncAttributeMaxDynamicSharedMemorySize, SMB);
    cudaFuncSetAttribute(gemm_k<EPI_BIAS,     false>, cudaFuncAttributeMaxDynamicSharedMemorySize, SMB);

    const dim3 cw(EB / 32, EB / 32, NLAY);
    const dim3 ct(32, 8);
    const dim3 gBig(EB / BN, MTOT / BM, 1);       // (8, 128)
    const dim3 gAtt(SEQ / BN, SEQ / BM, NBAT);    // (8, 8, 16)
    const dim3 gVt (SEQ / BN, EB / BM, NBAT);     // (8, 8, 16)
    const size_t sNE = (size_t)SEQ * EB;
    const size_t sSS = (size_t)SEQ * SEQ;
    const size_t sW  = (size_t)EB * EB;

    aw_k<<<dim3(EB / 128, NBAT), 128>>>(action_set, W_emb, aW);
    build_hs_k<<<MTOT, 256>>>(aW, W_emb, b_emb, wpe, Hs, Hh, Hl);
    convT_k<<<cw, ct>>>(Wq, Wqh, Wql, EB, EB);
    convT_k<<<cw, ct>>>(Wk, Wkh, Wkl, EB, EB);

    for (int l = 0; l < NLAY; ++l) {
        const size_t lw = (size_t)l * sW;
        // Q = H Wq,  K = H Wk   (split outputs)
        gemm_k<EPI_SPLIT, false><<<gBig, 256, SMB>>>(Hh, Hl, Wqh + lw, Wql + lw,
            nullptr, nullptr, Qh, Ql, EB, EB, 0, 0, 0);
        gemm_k<EPI_SPLIT, false><<<gBig, 256, SMB>>>(Hh, Hl, Wkh + lw, Wkl + lw,
            nullptr, nullptr, Kh, Kl, EB, EB, 0, 0, 0);
        if (l == 0) {   // remaining weight converts, before first use
            convT_k<<<cw, ct>>>(Wv, Wvh, Wvl, EB, EB);
            convT_k<<<cw, ct>>>(W1, W1h, W1l, EB, EB);
            convT_k<<<cw, ct>>>(W2, W2h, W2l, EB, EB);
        }
        // V^T directly: Vt[e,s] = sum_k Wv[k,e] H[s,k]   (batched, split out)
        gemm_k<EPI_SPLIT, false><<<gVt, 256, SMB>>>(Wvh + lw, Wvl + lw, Hh, Hl,
            nullptr, nullptr, Vth, Vtl, SEQ, EB, 0, sNE, sNE);
        // S = relu(Q K^T) * mask  -> bf16 hi/lo (above-diagonal tiles skipped)
        gemm_k<EPI_SC_SPLIT, false><<<gAtt, 256, SMB>>>(Qh, Ql, Kh, Kl,
            nullptr, nullptr, Sh, Sl, SEQ, EB, sNE, sNE, sSS);
        // T = S V (triangular K-loop)
        gemm_k<EPI_NONE, true><<<gAtt, 256, SMB>>>(Sh, Sl, Vth, Vtl,
            nullptr, T, nullptr, nullptr, EB, SEQ, sSS, sNE, sNE);
        ln_k<<<MTOT, 256>>>(Hs, T, ln1_g + (size_t)l * EB, ln1_b + (size_t)l * EB, Hh, Hl);
        gemm_k<EPI_BR_SPLIT, false><<<gBig, 256, SMB>>>(Hh, Hl, W1h + lw, W1l + lw,
            b1 + (size_t)l * EB, nullptr, Sh, Sl, EB, EB, 0, 0, 0);
        gemm_k<EPI_BIAS, false><<<gBig, 256, SMB>>>(Sh, Sl, W2h + lw, W2l + lw,
            b2 + (size_t)l * EB, T, nullptr, nullptr, EB, EB, 0, 0, 0);
        ln_k<<<MTOT, 256>>>(Hs, T, ln2_g + (size_t)l * EB, ln2_b + (size_t)l * EB, Hh, Hl);
    }

    pred_k<<<NBAT * HORZ, 256>>>(Hs, W_pred, b_pred, out);
}

// round 11
// speedup vs baseline: 2.1195x; 1.4329x over previous
#include <cuda_runtime.h>
#include <cuda_bf16.h>
#include <cstdint>
#include <cstddef>

// Problem constants
constexpr int EB   = 1024;
constexpr int NBAT = 16;
constexpr int SEQ  = 1024;
constexpr int NLAY = 12;
constexpr int MTOT = NBAT * SEQ;   // 16384
constexpr int AD   = 10;
constexpr int DA   = 640;
constexpr int HORZ = 512;

typedef __nv_bfloat16 bf16;

// Does this compilation pass support arch-specific sm_103a instructions?
#if defined(__CUDA_ARCH__) && (defined(__CUDA_ARCH_FEAT_SM103_ALL) || \
    (defined(__CUDA_ARCH_SPECIFIC__)) || (defined(__CUDA_ARCH_FAMILY_SPECIFIC__)))
#define TC_OK 1
#else
#define TC_OK 0
#endif

// ---------------- scratch (device globals; no allocations allowed) ----------
__device__ float d_Hs[(size_t)MTOT * EB];
__device__ float d_T [(size_t)MTOT * EB];
__device__ float d_aW[(size_t)NBAT * EB];

__device__ bf16 d_Hh[(size_t)MTOT * EB],  d_Hl[(size_t)MTOT * EB];
__device__ bf16 d_Qh[(size_t)MTOT * EB],  d_Ql[(size_t)MTOT * EB];
__device__ bf16 d_Kh[(size_t)MTOT * EB],  d_Kl[(size_t)MTOT * EB];
__device__ bf16 d_Vth[(size_t)MTOT * EB], d_Vtl[(size_t)MTOT * EB];
__device__ bf16 d_Sh[(size_t)NBAT * SEQ * SEQ], d_Sl[(size_t)NBAT * SEQ * SEQ];
__device__ bf16 d_Wq_h[(size_t)NLAY * EB * EB], d_Wq_l[(size_t)NLAY * EB * EB];
__device__ bf16 d_Wk_h[(size_t)NLAY * EB * EB], d_Wk_l[(size_t)NLAY * EB * EB];
__device__ bf16 d_Wv_h[(size_t)NLAY * EB * EB], d_Wv_l[(size_t)NLAY * EB * EB];
__device__ bf16 d_W1_h[(size_t)NLAY * EB * EB], d_W1_l[(size_t)NLAY * EB * EB];
__device__ bf16 d_W2_h[(size_t)NLAY * EB * EB], d_W2_l[(size_t)NLAY * EB * EB];

// ---------------- common helpers --------------------------------------------
__device__ __forceinline__ uint32_t cvs(const void* p) {
    return (uint32_t)__cvta_generic_to_shared(p);
}
__device__ __forceinline__ void split1(float x, bf16& h, bf16& l) {
    h = __float2bfloat16(x);
    l = __float2bfloat16(x - __bfloat162float(h));
}
#define CPA(dst, src) asm volatile("cp.async.cg.shared.global [%0],[%1],16;\n" :: "r"(dst), "l"(src))
#define CP_COMMIT()   asm volatile("cp.async.commit_group;\n")
#define CP_WAIT0()    asm volatile("cp.async.wait_group 0;\n")
#define CP_WAIT1()    asm volatile("cp.async.wait_group 1;\n")

// legacy mma.sync helpers (valid on all passes)
__device__ __forceinline__ void ldsm4(uint32_t* r, uint32_t addr) {
    asm volatile("ldmatrix.sync.aligned.m8n8.x4.shared.b16 {%0,%1,%2,%3},[%4];"
                 : "=r"(r[0]), "=r"(r[1]), "=r"(r[2]), "=r"(r[3]) : "r"(addr));
}
__device__ __forceinline__ void mma16816(float* d, const uint32_t* a,
                                         uint32_t b0, uint32_t b1) {
    asm volatile("mma.sync.aligned.m16n8k16.row.col.f32.bf16.bf16.f32 "
                 "{%0,%1,%2,%3},{%4,%5,%6,%7},{%8,%9},{%0,%1,%2,%3};"
                 : "+f"(d[0]), "+f"(d[1]), "+f"(d[2]), "+f"(d[3])
                 : "r"(a[0]), "r"(a[1]), "r"(a[2]), "r"(a[3]), "r"(b0), "r"(b1));
}

#if TC_OK
// ---------------- tcgen05 helpers (sm_103a-specific pass only) --------------
__device__ __forceinline__ uint32_t elect1() {
    uint32_t pred;
    asm volatile("{\n\t.reg .pred p;\n\telect.sync _|p, 0xFFFFFFFF;\n\t"
                 "selp.b32 %0, 1, 0, p;\n\t}" : "=r"(pred));
    return pred;
}
__device__ __forceinline__ uint64_t mk_desc(uint32_t base_addr) {
    constexpr uint64_t BASE =
        (uint64_t(2) << 61) | (uint64_t(1) << 46) | (uint64_t(64) << 32) | (uint64_t(1) << 16);
    return BASE | ((uint64_t)(base_addr >> 4) & 0x3FFF);
}
__device__ __forceinline__ void mma_f16_ss(uint32_t d, uint64_t ad, uint64_t bd,
                                           uint32_t idesc, uint32_t en) {
    asm volatile(
        "{\n\t.reg .pred p;\n\tsetp.ne.u32 p, %5, 0;\n\t"
        "tcgen05.mma.cta_group::1.kind::f16 [%0], %1, %2, %3, {%4,%4,%4,%4}, p;\n\t}"
        :: "r"(d), "l"(ad), "l"(bd), "r"(idesc), "r"(0u), "r"(en) : "memory");
}
__device__ __forceinline__ void tc_commit(uint32_t mbar) {
    asm volatile("tcgen05.commit.cta_group::1.mbarrier::arrive::one.shared::cluster.b64 [%0];"
                 :: "r"(mbar) : "memory");
}
__device__ __forceinline__ void mbar_init(uint32_t a, uint32_t cnt) {
    asm volatile("mbarrier.init.shared.b64 [%0], %1;" :: "r"(a), "r"(cnt) : "memory");
}
__device__ __forceinline__ void mbar_wait(uint32_t a, uint32_t parity) {
    asm volatile(
        "{\n\t.reg .pred P;\n\tW%=:\n\t"
        "mbarrier.try_wait.parity.acquire.cta.shared::cta.b64 P, [%0], %1, 0x989680;\n\t"
        "@!P bra W%=;\n\t}" :: "r"(a), "r"(parity) : "memory");
}
__device__ __forceinline__ void ld_tm32(uint32_t* r, uint32_t addr) {
    asm volatile(
        "tcgen05.ld.sync.aligned.32x32b.x32.b32 "
        "{%0,%1,%2,%3,%4,%5,%6,%7,%8,%9,%10,%11,%12,%13,%14,%15,"
        "%16,%17,%18,%19,%20,%21,%22,%23,%24,%25,%26,%27,%28,%29,%30,%31},[%32];"
        : "=r"(r[0]), "=r"(r[1]), "=r"(r[2]), "=r"(r[3]), "=r"(r[4]), "=r"(r[5]),
          "=r"(r[6]), "=r"(r[7]), "=r"(r[8]), "=r"(r[9]), "=r"(r[10]), "=r"(r[11]),
          "=r"(r[12]), "=r"(r[13]), "=r"(r[14]), "=r"(r[15]), "=r"(r[16]), "=r"(r[17]),
          "=r"(r[18]), "=r"(r[19]), "=r"(r[20]), "=r"(r[21]), "=r"(r[22]), "=r"(r[23]),
          "=r"(r[24]), "=r"(r[25]), "=r"(r[26]), "=r"(r[27]), "=r"(r[28]), "=r"(r[29]),
          "=r"(r[30]), "=r"(r[31])
        : "r"(addr));
}
#define TC_WAIT_LD()     asm volatile("tcgen05.wait::ld.sync.aligned;" ::: "memory")
#define TC_FENCE_AFTER() asm volatile("tcgen05.fence::after_thread_sync;" ::: "memory")
#define FENCE_ASYNC()    asm volatile("fence.proxy.async.shared::cta;" ::: "memory")
#endif  // TC_OK

// ---------------------------------------------------------------------------
// GEMM: C[M,N] = (Ah+Al)[M,K] @ (Bh+Bl)[N,K]^T  (3-term bf16x3, fp32 acc)
// tcgen05 path: CTA tile 128x128, BK=64 (SW128 rows), 3-stage cp.async,
// coalesced loads (8 lanes per 128B row) AND coalesced stores (epilogue
// bounces through per-warp smem scratch, then 128B-line uint4 stores).
// fallback path: mma.sync m16n8k16 (compile-only; tcgen05 wins fatbin dispatch)
// ---------------------------------------------------------------------------
constexpr int BM = 128, BN = 128;

// tcgen05 layout
constexpr int TC_BK   = 64;
constexpr int TC_PL   = BM * 128;           // plane bytes = 16384
constexpr int TC_STG  = 4 * TC_PL;          // stage bytes = 65536
constexpr int TC_HDR  = 1024;
constexpr int TC_NSTG = 3;
constexpr uint32_t IDESC =
    (1u << 4) | (1u << 7) | (1u << 10) | ((BN / 8) << 17) | ((BM / 16) << 24);
constexpr int TMEM_COLS_ALLOC = 128;

// epilogue scratch (reuses stage buffers after k-loop): per-warp 9216B
constexpr int EP_WSTRIDE = 9216;

// fallback layout
constexpr int FB_BK  = 32;
constexpr int FB_PL  = BM * 40 * 2;       // 10240
constexpr int FB_STG = 4 * FB_PL;         // 40960
constexpr int FB_STAGES = 3;

constexpr int SMB = 1024 + TC_HDR + TC_NSTG * TC_STG;   // 198656

enum { EPI_NONE = 0, EPI_BIAS = 1, EPI_SPLIT = 2, EPI_BR_SPLIT = 3, EPI_SC_SPLIT = 4 };

#if TC_OK
// Coalesced stage loader: per plane, 1024 16B-chunks; thread t takes chunks
// {t, t+256, t+512, t+768}. 8 consecutive lanes cover one 128B global row.
__device__ __forceinline__ void tc_load_stage(uint32_t stgBase,
    const bf16* __restrict__ Ah, const bf16* __restrict__ Al,
    const bf16* __restrict__ Bh, const bf16* __restrict__ Bl,
    int K, int k0, int row0, int col0, int tid)
{
    #pragma unroll
    for (int i = 0; i < 4; i++) {
        const int g   = i * 256 + tid;        // 0..1023
        const int row = g >> 3;               // 0..127
        const int c   = g & 7;                // 16B chunk within 128B row
        uint32_t off = (uint32_t)row * 128 + c * 16;
        uint32_t sw  = off ^ ((off >> 3) & 0x70);
        const size_t gA = (size_t)(row0 + row) * K + k0 + c * 8;
        const size_t gB = (size_t)(col0 + row) * K + k0 + c * 8;
        CPA(stgBase + 0 * TC_PL + sw, Ah + gA);
        CPA(stgBase + 1 * TC_PL + sw, Al + gA);
        CPA(stgBase + 2 * TC_PL + sw, Bh + gB);
        CPA(stgBase + 3 * TC_PL + sw, Bl + gB);
    }
}
#endif

__device__ __forceinline__ void fb_load_stage(uint32_t smBase,
    const bf16* __restrict__ Agh, const bf16* __restrict__ Agl,
    const bf16* __restrict__ Bgh, const bf16* __restrict__ Bgl,
    int K, int k0, int row0, int col0, int tid)
{
    const int row = tid >> 1;
    const int half = tid & 1;
    const uint32_t sm = smBase + row * 80 + half * 32;
    const size_t gA = (size_t)(row0 + row) * K + k0 + half * 16;
    const size_t gB = (size_t)(col0 + row) * K + k0 + half * 16;
    CPA(sm,                  Agh + gA); CPA(sm + 16,                  Agh + gA + 8);
    CPA(sm + FB_PL,          Agl + gA); CPA(sm + FB_PL + 16,          Agl + gA + 8);
    CPA(sm + 2 * FB_PL,      Bgh + gB); CPA(sm + 2 * FB_PL + 16,      Bgh + gB + 8);
    CPA(sm + 3 * FB_PL,      Bgl + gB); CPA(sm + 3 * FB_PL + 16,      Bgl + gB + 8);
}

template<int EPI, bool KLIM>
__global__ void __launch_bounds__(256, 1)
gemm_k(const bf16* __restrict__ Agh, const bf16* __restrict__ Agl,
       const bf16* __restrict__ Bgh, const bf16* __restrict__ Bgl,
       const float* __restrict__ bias,
       float* __restrict__ Cg, bf16* __restrict__ Chg, bf16* __restrict__ Clg,
       int N, int K, size_t sA, size_t sB, size_t sC)
{
    extern __shared__ char smem[];

    const int bx = blockIdx.x, by = blockIdx.y, bz = blockIdx.z;
    const int tid = threadIdx.x;
    const int lane = tid & 31, wid = tid >> 5;
    const int row0 = by * BM, col0 = bx * BN;

    // Score tiles strictly above the causal diagonal are NEVER read by the
    // S@V GEMM (its K-loop is clamped to (by+1)*BM), so skip entirely.
    if (EPI == EPI_SC_SPLIT && col0 >= row0 + BM) return;

    const bf16* Ah = Agh + (size_t)bz * sA;
    const bf16* Al = Agl + (size_t)bz * sA;
    const bf16* Bh = Bgh + (size_t)bz * sB;
    const bf16* Bl = Bgl + (size_t)bz * sB;

    int Keff = K;
    if (KLIM) { int km = (by + 1) * BM; Keff = km < K ? km : K; }

#if TC_OK
    // ======================= tcgen05 body ====================================
    const uint32_t sbRaw = cvs(smem);
    const uint32_t sb = (sbRaw + 1023u) & ~1023u;
    const uint32_t mDone = sb + 8;   // 3 done-mbarriers

    if (wid == 0)
        asm volatile("tcgen05.alloc.cta_group::1.sync.aligned.shared::cta.b32 [%0], %1;"
                     :: "r"(sb), "r"((uint32_t)TMEM_COLS_ALLOC) : "memory");
    if (tid == 0) { mbar_init(mDone + 0, 1); mbar_init(mDone + 8, 1); mbar_init(mDone + 16, 1); }
    __syncthreads();
    uint32_t tbase;
    asm volatile("ld.shared.b32 %0, [%1];" : "=r"(tbase) : "r"(sb));
    if (wid == 0)
        asm volatile("tcgen05.relinquish_alloc_permit.cta_group::1.sync.aligned;");

    const int NT = Keff / TC_BK;   // always >= 2 for our shapes

    // prologue: stages 0 and 1
    tc_load_stage(sb + TC_HDR,          Ah, Al, Bh, Bl, K, 0,     row0, col0, tid);
    CP_COMMIT();
    tc_load_stage(sb + TC_HDR + TC_STG, Ah, Al, Bh, Bl, K, TC_BK, row0, col0, tid);
    CP_COMMIT();

    int phm = 0;   // per-buffer done-phase bits

    for (int t = 0; t < NT; t++) {
        const int b = t % TC_NSTG;
        if (t + 1 < NT) { CP_WAIT1(); } else { CP_WAIT0(); }
        FENCE_ASYNC();
        __syncthreads();

        if (wid == 0) {
            TC_FENCE_AFTER();
            if (elect1()) {
                const uint32_t stg = sb + TC_HDR + b * TC_STG;
                const uint64_t adh = mk_desc(stg);
                const uint64_t adl = mk_desc(stg + TC_PL);
                const uint64_t bdh = mk_desc(stg + 2 * TC_PL);
                const uint64_t bdl = mk_desc(stg + 3 * TC_PL);
                #pragma unroll
                for (int ks = 0; ks < 4; ks++) {
                    uint32_t en0 = (t > 0 || ks > 0) ? 1u : 0u;
                    mma_f16_ss(tbase, adh + ks * 2, bdh + ks * 2, IDESC, en0);
                    mma_f16_ss(tbase, adh + ks * 2, bdl + ks * 2, IDESC, 1u);
                    mma_f16_ss(tbase, adl + ks * 2, bdh + ks * 2, IDESC, 1u);
                }
                tc_commit(mDone + b * 8);
            }
        }

        if (t + 2 < NT) {
            const int nb = (t + 2) % TC_NSTG;
            if (t >= 1) {   // buffer nb was used by MMA tile t-1: wait completion
                mbar_wait(mDone + nb * 8, (phm >> nb) & 1);
                phm ^= (1 << nb);
            }
            tc_load_stage(sb + TC_HDR + nb * TC_STG, Ah, Al, Bh, Bl, K,
                          (t + 2) * TC_BK, row0, col0, tid);
            CP_COMMIT();
        }
    }

    // final MMA completion (commit tracks all prior MMAs)
    const int lb = (NT - 1) % TC_NSTG;
    mbar_wait(mDone + lb * 8, (phm >> lb) & 1);
    TC_FENCE_AFTER();

    // ---- epilogue: TMEM -> regs -> per-warp smem scratch -> coalesced STG ---
    // warp w: rows (w&3)*32+lane, cols (w>>2)*64 .. +63.
    // stage buffers are dead after the final mbar_wait (all MMAs retired, all
    // own cp.asyncs drained at t=NT-1); each warp reuses only its own region.
    {
        const int wq = wid & 3;
        const int colh = (wid >> 2) * 64;
        const uint32_t toff = tbase + ((uint32_t)wq << 21) + (uint32_t)colh;

        uint32_t dr[64];
        ld_tm32(dr,      toff);
        ld_tm32(dr + 32, toff + 32);
        TC_WAIT_LD();

        char* wsc = smem + (sb - sbRaw) + TC_HDR + wid * EP_WSTRIDE;
        const int cbase = col0 + colh;
        const int r = row0 + wq * 32 + lane;
        const size_t gbase = (size_t)(row0 + wq * 32) * N + cbase;

        if (EPI == EPI_NONE || EPI == EPI_BIAS) {
            // rows padded to 272B in smem
            #pragma unroll
            for (int j = 0; j < 64; j += 4) {
                float4 v;
                v.x = __uint_as_float(dr[j + 0]);
                v.y = __uint_as_float(dr[j + 1]);
                v.z = __uint_as_float(dr[j + 2]);
                v.w = __uint_as_float(dr[j + 3]);
                if (EPI == EPI_BIAS) {
                    v.x += bias[cbase + j];     v.y += bias[cbase + j + 1];
                    v.z += bias[cbase + j + 2]; v.w += bias[cbase + j + 3];
                }
                *(float4*)(wsc + lane * 272 + j * 4) = v;
            }
            __syncwarp();
            float* Cb = Cg + (size_t)bz * sC;
            #pragma unroll
            for (int it = 0; it < 16; it++) {
                int rr = it * 2 + (lane >> 4);
                int ch = (lane & 15) * 16;
                float4 v = *(float4*)(wsc + rr * 272 + ch);
                *(float4*)((char*)(Cb + gbase + (size_t)rr * N) + ch) = v;
            }
        } else {
            // hi plane rows padded to 144B at wsc, lo plane at wsc+4608
            float inv = (EPI == EPI_SC_SPLIT) ? 1.0f / (float)(r + 1) : 0.f;
            #pragma unroll
            for (int j = 0; j < 64; j += 2) {
                float x0 = __uint_as_float(dr[j]);
                float x1 = __uint_as_float(dr[j + 1]);
                if (EPI == EPI_BR_SPLIT) {
                    x0 = fmaxf(x0 + bias[cbase + j], 0.f);
                    x1 = fmaxf(x1 + bias[cbase + j + 1], 0.f);
                } else if (EPI == EPI_SC_SPLIT) {
                    x0 = (cbase + j     <= r) ? fmaxf(x0, 0.f) * inv : 0.f;
                    x1 = (cbase + j + 1 <= r) ? fmaxf(x1, 0.f) * inv : 0.f;
                }
                bf16 h0, l0, h1, l1;
                split1(x0, h0, l0); split1(x1, h1, l1);
                __nv_bfloat162 vh; vh.x = h0; vh.y = h1;
                __nv_bfloat162 vl; vl.x = l0; vl.y = l1;
                *(__nv_bfloat162*)(wsc + lane * 144 + j * 2)        = vh;
                *(__nv_bfloat162*)(wsc + 4608 + lane * 144 + j * 2) = vl;
            }
            __syncwarp();
            bf16* ChB = Chg + (size_t)bz * sC;
            bf16* ClB = Clg + (size_t)bz * sC;
            #pragma unroll
            for (int it = 0; it < 8; it++) {
                int rr = it * 4 + (lane >> 3);
                int ch = (lane & 7) * 16;
                uint4 vH = *(uint4*)(wsc + rr * 144 + ch);
                uint4 vL = *(uint4*)(wsc + 4608 + rr * 144 + ch);
                *(uint4*)((char*)(ChB + gbase + (size_t)rr * N) + ch) = vH;
                *(uint4*)((char*)(ClB + gbase + (size_t)rr * N) + ch) = vL;
            }
        }
    }

    __syncthreads();
    if (wid == 0)
        asm volatile("tcgen05.dealloc.cta_group::1.sync.aligned.b32 %0, %1;"
                     :: "r"(tbase), "r"((uint32_t)TMEM_COLS_ALLOC));

#else
    // ======================= mma.sync fallback body ==========================
    const uint32_t smBase = cvs(smem);
    const int NT = Keff / FB_BK;

    float acc[2][8][4];
    #pragma unroll
    for (int i = 0; i < 2; i++)
        #pragma unroll
        for (int j = 0; j < 8; j++)
            #pragma unroll
            for (int q = 0; q < 4; q++) acc[i][j][q] = 0.f;

    const int wm = wid >> 1, wn = wid & 1;
    const int lr = lane & 15;
    const uint32_t colo = (uint32_t)(lane >> 4) * 16;

    #pragma unroll
    for (int s = 0; s < FB_STAGES - 1; s++) {
        if (s < NT) fb_load_stage(smBase + s * FB_STG, Ah, Al, Bh, Bl, K, s * FB_BK, row0, col0, tid);
        CP_COMMIT();
    }

    for (int t = 0; t < NT; t++) {
        CP_WAIT1();
        __syncthreads();

        int tp = t + FB_STAGES - 1;
        if (tp < NT)
            fb_load_stage(smBase + (tp % FB_STAGES) * FB_STG, Ah, Al, Bh, Bl, K, tp * FB_BK, row0, col0, tid);
        CP_COMMIT();

        const uint32_t stg = smBase + (t % FB_STAGES) * FB_STG;
        const uint32_t aRow = stg + (uint32_t)(wm * 32 + lr) * 80 + colo;
        const uint32_t bRow = stg + 2 * FB_PL + (uint32_t)(wn * 64 + lr) * 80 + colo;

        #pragma unroll
        for (int kk = 0; kk < 2; kk++) {
            const uint32_t ka = aRow + kk * 32, kb = bRow + kk * 32;
            uint32_t ah[2][4], al[2][4];
            #pragma unroll
            for (int mf = 0; mf < 2; mf++) {
                ldsm4(ah[mf], ka + mf * 16 * 80);
                ldsm4(al[mf], ka + FB_PL + mf * 16 * 80);
            }
            uint32_t bh[4][4], blf[4][4];
            #pragma unroll
            for (int g = 0; g < 4; g++) {
                ldsm4(bh[g], kb + g * 16 * 80);
                ldsm4(blf[g], kb + FB_PL + g * 16 * 80);
            }
            #pragma unroll
            for (int mf = 0; mf < 2; mf++) {
                #pragma unroll
                for (int g = 0; g < 4; g++) {
                    mma16816(acc[mf][2 * g],     ah[mf], bh[g][0],  bh[g][2]);
                    mma16816(acc[mf][2 * g],     ah[mf], blf[g][0], blf[g][2]);
                    mma16816(acc[mf][2 * g],     al[mf], bh[g][0],  bh[g][2]);
                    mma16816(acc[mf][2 * g + 1], ah[mf], bh[g][1],  bh[g][3]);
                    mma16816(acc[mf][2 * g + 1], ah[mf], blf[g][1], blf[g][3]);
                    mma16816(acc[mf][2 * g + 1], al[mf], bh[g][1],  bh[g][3]);
                }
            }
        }
        __syncthreads();
    }
    CP_WAIT0();

    float*  C  = (EPI == EPI_NONE || EPI == EPI_BIAS) ? Cg + (size_t)bz * sC : nullptr;
    bf16*   Ch = (EPI >= EPI_SPLIT) ? Chg + (size_t)bz * sC : nullptr;
    bf16*   Cl = (EPI >= EPI_SPLIT) ? Clg + (size_t)bz * sC : nullptr;
    const int qr = lane >> 2, qc = (lane & 3) * 2;
    #pragma unroll
    for (int mf = 0; mf < 2; mf++) {
        #pragma unroll
        for (int nf = 0; nf < 8; nf++) {
            int rA = row0 + wm * 32 + mf * 16 + qr;
            int cb = col0 + wn * 64 + nf * 8 + qc;
            #pragma unroll
            for (int half = 0; half < 2; half++) {
                int r = rA + half * 8;
                float x0 = acc[mf][nf][half * 2 + 0];
                float x1 = acc[mf][nf][half * 2 + 1];
                if (EPI == EPI_BIAS) {
                    x0 += bias[cb]; x1 += bias[cb + 1];
                } else if (EPI == EPI_BR_SPLIT) {
                    x0 = fmaxf(x0 + bias[cb], 0.f);
                    x1 = fmaxf(x1 + bias[cb + 1], 0.f);
                } else if (EPI == EPI_SC_SPLIT) {
                    float inv = 1.0f / (float)(r + 1);
                    x0 = (cb     <= r) ? fmaxf(x0, 0.f) * inv : 0.f;
                    x1 = (cb + 1 <= r) ? fmaxf(x1, 0.f) * inv : 0.f;
                }
                if (EPI == EPI_NONE || EPI == EPI_BIAS) {
                    float2 v; v.x = x0; v.y = x1;
                    *(float2*)&C[(size_t)r * N + cb] = v;
                } else {
                    bf16 h0, l0, h1, l1;
                    split1(x0, h0, l0); split1(x1, h1, l1);
                    __nv_bfloat162 vh; vh.x = h0; vh.y = h1;
                    __nv_bfloat162 vl; vl.x = l0; vl.y = l1;
                    *(__nv_bfloat162*)&Ch[(size_t)r * N + cb] = vh;
                    *(__nv_bfloat162*)&Cl[(size_t)r * N + cb] = vl;
                }
            }
        }
    }
#endif
}

// ---------------------------------------------------------------------------
// Transpose + split-convert: in[z][R][C] fp32 -> oh/ol[z][C][R] bf16
// (weights only, once per launch)
// ---------------------------------------------------------------------------
__global__ void convT_k(const float* __restrict__ in, bf16* __restrict__ oh,
                        bf16* __restrict__ ol, int R, int C)
{
    const int z = blockIdx.z;
    in += (size_t)z * R * C;
    oh += (size_t)z * R * C;
    ol += (size_t)z * R * C;
    __shared__ float t[32][33];
    const int c0 = blockIdx.x * 32, r0 = blockIdx.y * 32;
    const int tx = threadIdx.x, ty = threadIdx.y;
    #pragma unroll
    for (int i = 0; i < 4; i++)
        t[ty + i * 8][tx] = in[(size_t)(r0 + ty + i * 8) * C + c0 + tx];
    __syncthreads();
    #pragma unroll
    for (int i = 0; i < 4; i++) {
        float v = t[tx][ty + i * 8];
        int cc = c0 + ty + i * 8, rr = r0 + tx;
        bf16 h, l; split1(v, h, l);
        oh[(size_t)cc * R + rr] = h;
        ol[(size_t)cc * R + rr] = l;
    }
}

// ---------------------------------------------------------------------------
// Fused residual + LayerNorm, emitting fp32 + bf16 hi/lo
// ---------------------------------------------------------------------------
__global__ void ln_k(float* __restrict__ Hs, const float* __restrict__ Res,
                     const float* __restrict__ g, const float* __restrict__ be,
                     bf16* __restrict__ Hh, bf16* __restrict__ Hl)
{
    int row = blockIdx.x;
    int tid = threadIdx.x;
    int lane = tid & 31, warp = tid >> 5;
    __shared__ float sm[8];

    float4 x = *(float4*)&Hs[(size_t)row * EB + tid * 4];
    float4 rr = *(const float4*)&Res[(size_t)row * EB + tid * 4];
    x.x += rr.x; x.y += rr.y; x.z += rr.z; x.w += rr.w;

    float s = x.x + x.y + x.z + x.w;
    #pragma unroll
    for (int o = 16; o; o >>= 1) s += __shfl_down_sync(0xffffffffu, s, o);
    if (!lane) sm[warp] = s;
    __syncthreads();
    float mu;
    {
        float t = (lane < 8) ? sm[lane] : 0.f;
        #pragma unroll
        for (int o = 4; o; o >>= 1) t += __shfl_down_sync(0xffffffffu, t, o);
        mu = __shfl_sync(0xffffffffu, t, 0) * (1.0f / 1024.0f);
    }
    __syncthreads();

    float dx0 = x.x - mu, dx1 = x.y - mu, dx2 = x.z - mu, dx3 = x.w - mu;
    float sq = dx0 * dx0 + dx1 * dx1 + dx2 * dx2 + dx3 * dx3;
    #pragma unroll
    for (int o = 16; o; o >>= 1) sq += __shfl_down_sync(0xffffffffu, sq, o);
    if (!lane) sm[warp] = sq;
    __syncthreads();
    float rstd;
    {
        float t = (lane < 8) ? sm[lane] : 0.f;
        #pragma unroll
        for (int o = 4; o; o >>= 1) t += __shfl_down_sync(0xffffffffu, t, o);
        float var = __shfl_sync(0xffffffffu, t, 0) * (1.0f / 1024.0f);
        rstd = rsqrtf(var + 1e-5f);
    }

    float4 gv = *(const float4*)&g[tid * 4];
    float4 bv = *(const float4*)&be[tid * 4];
    float4 o;
    o.x = dx0 * rstd * gv.x + bv.x;
    o.y = dx1 * rstd * gv.y + bv.y;
    o.z = dx2 * rstd * gv.z + bv.z;
    o.w = dx3 * rstd * gv.w + bv.w;
    *(float4*)&Hs[(size_t)row * EB + tid * 4] = o;

    bf16 h0, l0, h1, l1, h2, l2, h3, l3;
    split1(o.x, h0, l0); split1(o.y, h1, l1);
    split1(o.z, h2, l2); split1(o.w, h3, l3);
    __nv_bfloat162 a0; a0.x = h0; a0.y = h1;
    __nv_bfloat162 a1; a1.x = h2; a1.y = h3;
    __nv_bfloat162 b0; b0.x = l0; b0.y = l1;
    __nv_bfloat162 b1; b1.x = l2; b1.y = l3;
    *(__nv_bfloat162*)&Hh[(size_t)row * EB + tid * 4]     = a0;
    *(__nv_bfloat162*)&Hh[(size_t)row * EB + tid * 4 + 2] = a1;
    *(__nv_bfloat162*)&Hl[(size_t)row * EB + tid * 4]     = b0;
    *(__nv_bfloat162*)&Hl[(size_t)row * EB + tid * 4 + 2] = b1;
}

// ---------------------------------------------------------------------------
// Embedding
// ---------------------------------------------------------------------------
__global__ void aw_k(const float* __restrict__ act, const float* __restrict__ Wemb,
                     float* __restrict__ aW)
{
    int e = blockIdx.x * 128 + threadIdx.x;
    int b = blockIdx.y;
    const float* a = act + (size_t)b * DA;
    float s = 0.f;
    #pragma unroll 4
    for (int i = 0; i < DA; i++)
        s = fmaf(a[i], Wemb[(size_t)i * EB + e], s);
    aW[(size_t)b * EB + e] = s;
}

__global__ void build_hs_k(const float* __restrict__ aW, const float* __restrict__ Wemb,
                           const float* __restrict__ bemb, const float* __restrict__ wpe,
                           float* __restrict__ Hs, bf16* __restrict__ Hh, bf16* __restrict__ Hl)
{
    int row = blockIdx.x;
    int n = row & (SEQ - 1), b = row >> 10;
    int e = threadIdx.x * 4;
    float4 w1 = *(const float4*)&Wemb[(size_t)651 * EB + e];
    float4 w2 = *(const float4*)&Wemb[(size_t)652 * EB + e];
    float4 bb = *(const float4*)&bemb[e];
    float4 pp = *(const float4*)&wpe[(size_t)n * EB + e];
    float pos = (float)(n + 1);
    float4 v;
    v.x = w1.x + pos * w2.x + bb.x + pp.x;
    v.y = w1.y + pos * w2.y + bb.y + pp.y;
    v.z = w1.z + pos * w2.z + bb.z + pp.z;
    v.w = w1.w + pos * w2.w + bb.w + pp.w;
    if (!(n & 1)) {
        float4 av = *(const float4*)&aW[(size_t)b * EB + e];
        v.x += av.x; v.y += av.y; v.z += av.z; v.w += av.w;
    }
    *(float4*)&Hs[(size_t)row * EB + e] = v;
    bf16 h, l;
    split1(v.x, h, l); Hh[(size_t)row * EB + e + 0] = h; Hl[(size_t)row * EB + e + 0] = l;
    split1(v.y, h, l); Hh[(size_t)row * EB + e + 1] = h; Hl[(size_t)row * EB + e + 1] = l;
    split1(v.z, h, l); Hh[(size_t)row * EB + e + 2] = h; Hl[(size_t)row * EB + e + 2] = l;
    split1(v.w, h, l); Hh[(size_t)row * EB + e + 3] = h; Hl[(size_t)row * EB + e + 3] = l;
}

// ---------------------------------------------------------------------------
// Prediction head
// ---------------------------------------------------------------------------
__global__ void pred_k(const float* __restrict__ Hs, const float* __restrict__ Wp,
                       const float* __restrict__ bp, float* __restrict__ out)
{
    int idx = blockIdx.x;
    int b = idx >> 9, h = idx & 511;
    const float* x = Hs + ((size_t)(b * SEQ + 2 * h)) * EB;
    int tid = threadIdx.x, lane = tid & 31, warp = tid >> 5;

    float4 xv = *(const float4*)&x[tid * 4];
    float xs[4] = { xv.x, xv.y, xv.z, xv.w };
    const float* w0 = Wp + (size_t)(tid * 4) * AD;

    float p[AD];
    #pragma unroll
    for (int ad = 0; ad < AD; ++ad) p[ad] = 0.f;
    #pragma unroll
    for (int t = 0; t < 4; t++)
        #pragma unroll
        for (int ad = 0; ad < AD; ++ad)
            p[ad] = fmaf(xs[t], w0[t * AD + ad], p[ad]);

    __shared__ float red[8][AD];
    #pragma unroll
    for (int ad = 0; ad < AD; ad++) {
        float s = p[ad];
        #pragma unroll
        for (int o = 16; o; o >>= 1) s += __shfl_down_sync(0xffffffffu, s, o);
        if (!lane) red[warp][ad] = s;
    }
    __syncthreads();
    if (tid < AD) {
        float s = 0.f;
        #pragma unroll
        for (int w = 0; w < 8; w++) s += red[w][tid];
        out[(size_t)idx * AD + tid] = s + bp[tid];
    }
}

// ---------------------------------------------------------------------------
extern "C" void kernel_launch(void* const* d_in, const int* in_sizes, int n_in,
                              void* d_out, int out_size)
{
    const float* action_set = (const float*)d_in[0];
    const float* wpe    = (const float*)d_in[2];
    const float* W_emb  = (const float*)d_in[3];
    const float* b_emb  = (const float*)d_in[4];
    const float* Wq     = (const float*)d_in[5];
    const float* Wk     = (const float*)d_in[6];
    const float* Wv     = (const float*)d_in[7];
    const float* ln1_g  = (const float*)d_in[8];
    const float* ln1_b  = (const float*)d_in[9];
    const float* W1     = (const float*)d_in[10];
    const float* b1     = (const float*)d_in[11];
    const float* W2     = (const float*)d_in[12];
    const float* b2     = (const float*)d_in[13];
    const float* ln2_g  = (const float*)d_in[14];
    const float* ln2_b  = (const float*)d_in[15];
    const float* W_pred = (const float*)d_in[16];
    const float* b_pred = (const float*)d_in[17];
    float* out = (float*)d_out;

    float *Hs, *T, *aW;
    cudaGetSymbolAddress((void**)&Hs, d_Hs);
    cudaGetSymbolAddress((void**)&T,  d_T);
    cudaGetSymbolAddress((void**)&aW, d_aW);
    bf16 *Hh, *Hl, *Qh, *Ql, *Kh, *Kl, *Vth, *Vtl, *Sh, *Sl;
    cudaGetSymbolAddress((void**)&Hh, d_Hh);   cudaGetSymbolAddress((void**)&Hl, d_Hl);
    cudaGetSymbolAddress((void**)&Qh, d_Qh);   cudaGetSymbolAddress((void**)&Ql, d_Ql);
    cudaGetSymbolAddress((void**)&Kh, d_Kh);   cudaGetSymbolAddress((void**)&Kl, d_Kl);
    cudaGetSymbolAddress((void**)&Vth, d_Vth); cudaGetSymbolAddress((void**)&Vtl, d_Vtl);
    cudaGetSymbolAddress((void**)&Sh, d_Sh);   cudaGetSymbolAddress((void**)&Sl, d_Sl);
    bf16 *Wqh, *Wql, *Wkh, *Wkl, *Wvh, *Wvl, *W1h, *W1l, *W2h, *W2l;
    cudaGetSymbolAddress((void**)&Wqh, d_Wq_h); cudaGetSymbolAddress((void**)&Wql, d_Wq_l);
    cudaGetSymbolAddress((void**)&Wkh, d_Wk_h); cudaGetSymbolAddress((void**)&Wkl, d_Wk_l);
    cudaGetSymbolAddress((void**)&Wvh, d_Wv_h); cudaGetSymbolAddress((void**)&Wvl, d_Wv_l);
    cudaGetSymbolAddress((void**)&W1h, d_W1_h); cudaGetSymbolAddress((void**)&W1l, d_W1_l);
    cudaGetSymbolAddress((void**)&W2h, d_W2_h); cudaGetSymbolAddress((void**)&W2l, d_W2_l);

    cudaFuncSetAttribute(gemm_k<EPI_SPLIT,    false>, cudaFuncAttributeMaxDynamicSharedMemorySize, SMB);
    cudaFuncSetAttribute(gemm_k<EPI_SC_SPLIT, false>, cudaFuncAttributeMaxDynamicSharedMemorySize, SMB);
    cudaFuncSetAttribute(gemm_k<EPI_NONE,     true >, cudaFuncAttributeMaxDynamicSharedMemorySize, SMB);
    cudaFuncSetAttribute(gemm_k<EPI_BR_SPLIT, false>, cudaFuncAttributeMaxDynamicSharedMemorySize, SMB);
    cudaFuncSetAttribute(gemm_k<EPI_BIAS,     false>, cudaFuncAttributeMaxDynamicSharedMemorySize, SMB);

    const dim3 cw(EB / 32, EB / 32, NLAY);
    const dim3 ct(32, 8);
    const dim3 gBig(EB / BN, MTOT / BM, 1);       // (8, 128)
    const dim3 gAtt(SEQ / BN, SEQ / BM, NBAT);    // (8, 8, 16)
    const dim3 gVt (SEQ / BN, EB / BM, NBAT);     // (8, 8, 16)
    const size_t sNE = (size_t)SEQ * EB;
    const size_t sSS = (size_t)SEQ * SEQ;
    const size_t sW  = (size_t)EB * EB;

    aw_k<<<dim3(EB / 128, NBAT), 128>>>(action_set, W_emb, aW);
    build_hs_k<<<MTOT, 256>>>(aW, W_emb, b_emb, wpe, Hs, Hh, Hl);
    convT_k<<<cw, ct>>>(Wq, Wqh, Wql, EB, EB);
    convT_k<<<cw, ct>>>(Wk, Wkh, Wkl, EB, EB);

    for (int l = 0; l < NLAY; ++l) {
        const size_t lw = (size_t)l * sW;
        // Q = H Wq,  K = H Wk   (split outputs)
        gemm_k<EPI_SPLIT, false><<<gBig, 256, SMB>>>(Hh, Hl, Wqh + lw, Wql + lw,
            nullptr, nullptr, Qh, Ql, EB, EB, 0, 0, 0);
        gemm_k<EPI_SPLIT, false><<<gBig, 256, SMB>>>(Hh, Hl, Wkh + lw, Wkl + lw,
            nullptr, nullptr, Kh, Kl, EB, EB, 0, 0, 0);
        if (l == 0) {   // remaining weight converts, before first use
            convT_k<<<cw, ct>>>(Wv, Wvh, Wvl, EB, EB);
            convT_k<<<cw, ct>>>(W1, W1h, W1l, EB, EB);
            convT_k<<<cw, ct>>>(W2, W2h, W2l, EB, EB);
        }
        // V^T directly: Vt[e,s] = sum_k Wv[k,e] H[s,k]   (batched, split out)
        gemm_k<EPI_SPLIT, false><<<gVt, 256, SMB>>>(Wvh + lw, Wvl + lw, Hh, Hl,
            nullptr, nullptr, Vth, Vtl, SEQ, EB, 0, sNE, sNE);
        // S = relu(Q K^T) * mask  -> bf16 hi/lo (above-diagonal tiles skipped)
        gemm_k<EPI_SC_SPLIT, false><<<gAtt, 256, SMB>>>(Qh, Ql, Kh, Kl,
            nullptr, nullptr, Sh, Sl, SEQ, EB, sNE, sNE, sSS);
        // T = S V (triangular K-loop)
        gemm_k<EPI_NONE, true><<<gAtt, 256, SMB>>>(Sh, Sl, Vth, Vtl,
            nullptr, T, nullptr, nullptr, EB, SEQ, sSS, sNE, sNE);
        ln_k<<<MTOT, 256>>>(Hs, T, ln1_g + (size_t)l * EB, ln1_b + (size_t)l * EB, Hh, Hl);
        gemm_k<EPI_BR_SPLIT, false><<<gBig, 256, SMB>>>(Hh, Hl, W1h + lw, W1l + lw,
            b1 + (size_t)l * EB, nullptr, Sh, Sl, EB, EB, 0, 0, 0);
        gemm_k<EPI_BIAS, false><<<gBig, 256, SMB>>>(Sh, Sl, W2h + lw, W2l + lw,
            b2 + (size_t)l * EB, T, nullptr, nullptr, EB, EB, 0, 0, 0);
        ln_k<<<MTOT, 256>>>(Hs, T, ln2_g + (size_t)l * EB, ln2_b + (size_t)l * EB, Hh, Hl);
    }

    pred_k<<<NBAT * HORZ, 256>>>(Hs, W_pred, b_pred, out);
}

// round 13
// speedup vs baseline: 2.1698x; 1.0237x over previous
#include <cuda_runtime.h>
#include <cuda_bf16.h>
#include <cstdint>
#include <cstddef>

// Problem constants
constexpr int EB   = 1024;
constexpr int NBAT = 16;
constexpr int SEQ  = 1024;
constexpr int NLAY = 12;
constexpr int MTOT = NBAT * SEQ;   // 16384
constexpr int AD   = 10;
constexpr int DA   = 640;
constexpr int HORZ = 512;

typedef __nv_bfloat16 bf16;

#if defined(__CUDA_ARCH__) && (defined(__CUDA_ARCH_FEAT_SM103_ALL) || \
    (defined(__CUDA_ARCH_SPECIFIC__)) || (defined(__CUDA_ARCH_FAMILY_SPECIFIC__)))
#define TC_OK 1
#else
#define TC_OK 0
#endif

// ---------------- scratch (device globals; no allocations allowed) ----------
__device__ float d_T [(size_t)MTOT * EB];
__device__ float d_aW[(size_t)NBAT * EB];

__device__ bf16 d_Hh[(size_t)MTOT * EB],  d_Hl[(size_t)MTOT * EB];
__device__ bf16 d_Qh[(size_t)MTOT * EB],  d_Ql[(size_t)MTOT * EB];
__device__ bf16 d_Kh[(size_t)MTOT * EB],  d_Kl[(size_t)MTOT * EB];
__device__ bf16 d_Vth[(size_t)MTOT * EB], d_Vtl[(size_t)MTOT * EB];
__device__ bf16 d_Sh[(size_t)NBAT * SEQ * SEQ], d_Sl[(size_t)NBAT * SEQ * SEQ];
// transposed split weights
__device__ bf16 d_Wq_h[(size_t)NLAY * EB * EB], d_Wq_l[(size_t)NLAY * EB * EB];
__device__ bf16 d_Wk_h[(size_t)NLAY * EB * EB], d_Wk_l[(size_t)NLAY * EB * EB];
__device__ bf16 d_Wv_h[(size_t)NLAY * EB * EB], d_Wv_l[(size_t)NLAY * EB * EB];
__device__ bf16 d_W1_h[(size_t)NLAY * EB * EB], d_W1_l[(size_t)NLAY * EB * EB];
__device__ bf16 d_W2_h[(size_t)NLAY * EB * EB], d_W2_l[(size_t)NLAY * EB * EB];

// ---------------- common helpers --------------------------------------------
__device__ __forceinline__ uint32_t cvs(const void* p) {
    return (uint32_t)__cvta_generic_to_shared(p);
}
__device__ __forceinline__ void split1(float x, bf16& h, bf16& l) {
    h = __float2bfloat16(x);
    l = __float2bfloat16(x - __bfloat162float(h));
}
#define CPA(dst, src) asm volatile("cp.async.cg.shared.global [%0],[%1],16;\n" :: "r"(dst), "l"(src))
#define CP_COMMIT()   asm volatile("cp.async.commit_group;\n")
#define CP_WAIT0()    asm volatile("cp.async.wait_group 0;\n")
#define CP_WAIT1()    asm volatile("cp.async.wait_group 1;\n")

__device__ __forceinline__ void ldsm4(uint32_t* r, uint32_t addr) {
    asm volatile("ldmatrix.sync.aligned.m8n8.x4.shared.b16 {%0,%1,%2,%3},[%4];"
                 : "=r"(r[0]), "=r"(r[1]), "=r"(r[2]), "=r"(r[3]) : "r"(addr));
}
__device__ __forceinline__ void mma16816(float* d, const uint32_t* a,
                                         uint32_t b0, uint32_t b1) {
    asm volatile("mma.sync.aligned.m16n8k16.row.col.f32.bf16.bf16.f32 "
                 "{%0,%1,%2,%3},{%4,%5,%6,%7},{%8,%9},{%0,%1,%2,%3};"
                 : "+f"(d[0]), "+f"(d[1]), "+f"(d[2]), "+f"(d[3])
                 : "r"(a[0]), "r"(a[1]), "r"(a[2]), "r"(a[3]), "r"(b0), "r"(b1));
}

#if TC_OK
__device__ __forceinline__ uint32_t elect1() {
    uint32_t pred;
    asm volatile("{\n\t.reg .pred p;\n\telect.sync _|p, 0xFFFFFFFF;\n\t"
                 "selp.b32 %0, 1, 0, p;\n\t}" : "=r"(pred));
    return pred;
}
__device__ __forceinline__ uint64_t mk_desc(uint32_t base_addr) {
    constexpr uint64_t BASE =
        (uint64_t(2) << 61) | (uint64_t(1) << 46) | (uint64_t(64) << 32) | (uint64_t(1) << 16);
    return BASE | ((uint64_t)(base_addr >> 4) & 0x3FFF);
}
__device__ __forceinline__ void mma_f16_ss(uint32_t d, uint64_t ad, uint64_t bd,
                                           uint32_t idesc, uint32_t en) {
    asm volatile(
        "{\n\t.reg .pred p;\n\tsetp.ne.u32 p, %5, 0;\n\t"
        "tcgen05.mma.cta_group::1.kind::f16 [%0], %1, %2, %3, {%4,%4,%4,%4}, p;\n\t}"
        :: "r"(d), "l"(ad), "l"(bd), "r"(idesc), "r"(0u), "r"(en) : "memory");
}
__device__ __forceinline__ void tc_commit(uint32_t mbar) {
    asm volatile("tcgen05.commit.cta_group::1.mbarrier::arrive::one.shared::cluster.b64 [%0];"
                 :: "r"(mbar) : "memory");
}
__device__ __forceinline__ void mbar_init(uint32_t a, uint32_t cnt) {
    asm volatile("mbarrier.init.shared.b64 [%0], %1;" :: "r"(a), "r"(cnt) : "memory");
}
__device__ __forceinline__ void mbar_wait(uint32_t a, uint32_t parity) {
    asm volatile(
        "{\n\t.reg .pred P;\n\tW%=:\n\t"
        "mbarrier.try_wait.parity.acquire.cta.shared::cta.b64 P, [%0], %1, 0x989680;\n\t"
        "@!P bra W%=;\n\t}" :: "r"(a), "r"(parity) : "memory");
}
__device__ __forceinline__ void ld_tm32(uint32_t* r, uint32_t addr) {
    asm volatile(
        "tcgen05.ld.sync.aligned.32x32b.x32.b32 "
        "{%0,%1,%2,%3,%4,%5,%6,%7,%8,%9,%10,%11,%12,%13,%14,%15,"
        "%16,%17,%18,%19,%20,%21,%22,%23,%24,%25,%26,%27,%28,%29,%30,%31},[%32];"
        : "=r"(r[0]), "=r"(r[1]), "=r"(r[2]), "=r"(r[3]), "=r"(r[4]), "=r"(r[5]),
          "=r"(r[6]), "=r"(r[7]), "=r"(r[8]), "=r"(r[9]), "=r"(r[10]), "=r"(r[11]),
          "=r"(r[12]), "=r"(r[13]), "=r"(r[14]), "=r"(r[15]), "=r"(r[16]), "=r"(r[17]),
          "=r"(r[18]), "=r"(r[19]), "=r"(r[20]), "=r"(r[21]), "=r"(r[22]), "=r"(r[23]),
          "=r"(r[24]), "=r"(r[25]), "=r"(r[26]), "=r"(r[27]), "=r"(r[28]), "=r"(r[29]),
          "=r"(r[30]), "=r"(r[31])
        : "r"(addr));
}
#define TC_WAIT_LD()     asm volatile("tcgen05.wait::ld.sync.aligned;" ::: "memory")
#define TC_FENCE_AFTER() asm volatile("tcgen05.fence::after_thread_sync;" ::: "memory")
#define FENCE_ASYNC()    asm volatile("fence.proxy.async.shared::cta;" ::: "memory")
#endif  // TC_OK

// ---------------------------------------------------------------------------
// GEMM: C[M,N] = (Ah+Al)[M,K] @ (Bh+Bl)[N,K]^T  (3-term bf16x3, fp32 acc)
// tcgen05: 128x128 tile, BK=64, 3-stage cp.async, coalesced loads + stores.
// ---------------------------------------------------------------------------
constexpr int BM = 128, BN = 128;

constexpr int TC_BK   = 64;
constexpr int TC_PL   = BM * 128;
constexpr int TC_STG  = 4 * TC_PL;
constexpr int TC_HDR  = 1024;
constexpr int TC_NSTG = 3;
constexpr uint32_t IDESC =
    (1u << 4) | (1u << 7) | (1u << 10) | ((BN / 8) << 17) | ((BM / 16) << 24);
constexpr int TMEM_COLS_ALLOC = 128;
constexpr int EP_WSTRIDE = 9216;

constexpr int FB_BK  = 32;
constexpr int FB_PL  = BM * 40 * 2;
constexpr int FB_STG = 4 * FB_PL;
constexpr int FB_STAGES = 3;

constexpr int SMB = 1024 + TC_HDR + TC_NSTG * TC_STG;   // 198656

enum { EPI_NONE = 0, EPI_BIAS = 1, EPI_SPLIT = 2, EPI_BR_SPLIT = 3, EPI_SC_SPLIT = 4 };

#if TC_OK
__device__ __forceinline__ void tc_load_stage(uint32_t stgBase,
    const bf16* __restrict__ Ah, const bf16* __restrict__ Al,
    const bf16* __restrict__ Bh, const bf16* __restrict__ Bl,
    int K, int k0, int row0, int col0, int tid)
{
    #pragma unroll
    for (int i = 0; i < 4; i++) {
        const int g   = i * 256 + tid;
        const int row = g >> 3;
        const int c   = g & 7;
        uint32_t off = (uint32_t)row * 128 + c * 16;
        uint32_t sw  = off ^ ((off >> 3) & 0x70);
        const size_t gA = (size_t)(row0 + row) * K + k0 + c * 8;
        const size_t gB = (size_t)(col0 + row) * K + k0 + c * 8;
        CPA(stgBase + 0 * TC_PL + sw, Ah + gA);
        CPA(stgBase + 1 * TC_PL + sw, Al + gA);
        CPA(stgBase + 2 * TC_PL + sw, Bh + gB);
        CPA(stgBase + 3 * TC_PL + sw, Bl + gB);
    }
}
#endif

__device__ __forceinline__ void fb_load_stage(uint32_t smBase,
    const bf16* __restrict__ Agh, const bf16* __restrict__ Agl,
    const bf16* __restrict__ Bgh, const bf16* __restrict__ Bgl,
    int K, int k0, int row0, int col0, int tid)
{
    const int row = tid >> 1;
    const int half = tid & 1;
    const uint32_t sm = smBase + row * 80 + half * 32;
    const size_t gA = (size_t)(row0 + row) * K + k0 + half * 16;
    const size_t gB = (size_t)(col0 + row) * K + k0 + half * 16;
    CPA(sm,                  Agh + gA); CPA(sm + 16,                  Agh + gA + 8);
    CPA(sm + FB_PL,          Agl + gA); CPA(sm + FB_PL + 16,          Agl + gA + 8);
    CPA(sm + 2 * FB_PL,      Bgh + gB); CPA(sm + 2 * FB_PL + 16,      Bgh + gB + 8);
    CPA(sm + 3 * FB_PL,      Bgl + gB); CPA(sm + 3 * FB_PL + 16,      Bgl + gB + 8);
}

template<int EPI, bool KLIM>
__global__ void __launch_bounds__(256, 1)
gemm_k(const bf16* __restrict__ Agh, const bf16* __restrict__ Agl,
       const bf16* __restrict__ Bgh, const bf16* __restrict__ Bgl,
       const float* __restrict__ bias,
       float* __restrict__ Cg, bf16* __restrict__ Chg, bf16* __restrict__ Clg,
       int N, int K, size_t sA, size_t sB, size_t sC)
{
    extern __shared__ char smem[];

    const int bx = blockIdx.x, by = blockIdx.y, bz = blockIdx.z;
    const int tid = threadIdx.x;
    const int lane = tid & 31, wid = tid >> 5;
    const int row0 = by * BM, col0 = bx * BN;

    if (EPI == EPI_SC_SPLIT && col0 >= row0 + BM) return;

    const bf16* Ah = Agh + (size_t)bz * sA;
    const bf16* Al = Agl + (size_t)bz * sA;
    const bf16* Bh = Bgh + (size_t)bz * sB;
    const bf16* Bl = Bgl + (size_t)bz * sB;

    int Keff = K;
    if (KLIM) { int km = (by + 1) * BM; Keff = km < K ? km : K; }

#if TC_OK
    const uint32_t sbRaw = cvs(smem);
    const uint32_t sb = (sbRaw + 1023u) & ~1023u;
    const uint32_t mDone = sb + 8;

    if (wid == 0)
        asm volatile("tcgen05.alloc.cta_group::1.sync.aligned.shared::cta.b32 [%0], %1;"
                     :: "r"(sb), "r"((uint32_t)TMEM_COLS_ALLOC) : "memory");
    if (tid == 0) { mbar_init(mDone + 0, 1); mbar_init(mDone + 8, 1); mbar_init(mDone + 16, 1); }
    __syncthreads();
    uint32_t tbase;
    asm volatile("ld.shared.b32 %0, [%1];" : "=r"(tbase) : "r"(sb));
    if (wid == 0)
        asm volatile("tcgen05.relinquish_alloc_permit.cta_group::1.sync.aligned;");

    const int NT = Keff / TC_BK;

    tc_load_stage(sb + TC_HDR,          Ah, Al, Bh, Bl, K, 0,     row0, col0, tid);
    CP_COMMIT();
    tc_load_stage(sb + TC_HDR + TC_STG, Ah, Al, Bh, Bl, K, TC_BK, row0, col0, tid);
    CP_COMMIT();

    int phm = 0;

    for (int t = 0; t < NT; t++) {
        const int b = t % TC_NSTG;
        if (t + 1 < NT) { CP_WAIT1(); } else { CP_WAIT0(); }
        FENCE_ASYNC();
        __syncthreads();

        if (wid == 0) {
            TC_FENCE_AFTER();
            if (elect1()) {
                const uint32_t stg = sb + TC_HDR + b * TC_STG;
                const uint64_t adh = mk_desc(stg);
                const uint64_t adl = mk_desc(stg + TC_PL);
                const uint64_t bdh = mk_desc(stg + 2 * TC_PL);
                const uint64_t bdl = mk_desc(stg + 3 * TC_PL);
                #pragma unroll
                for (int ks = 0; ks < 4; ks++) {
                    uint32_t en0 = (t > 0 || ks > 0) ? 1u : 0u;
                    mma_f16_ss(tbase, adh + ks * 2, bdh + ks * 2, IDESC, en0);
                    mma_f16_ss(tbase, adh + ks * 2, bdl + ks * 2, IDESC, 1u);
                    mma_f16_ss(tbase, adl + ks * 2, bdh + ks * 2, IDESC, 1u);
                }
                tc_commit(mDone + b * 8);
            }
        }

        if (t + 2 < NT) {
            const int nb = (t + 2) % TC_NSTG;
            if (t >= 1) {
                mbar_wait(mDone + nb * 8, (phm >> nb) & 1);
                phm ^= (1 << nb);
            }
            tc_load_stage(sb + TC_HDR + nb * TC_STG, Ah, Al, Bh, Bl, K,
                          (t + 2) * TC_BK, row0, col0, tid);
            CP_COMMIT();
        }
    }

    const int lb = (NT - 1) % TC_NSTG;
    mbar_wait(mDone + lb * 8, (phm >> lb) & 1);
    TC_FENCE_AFTER();

    // ---- epilogue: TMEM -> regs -> per-warp smem scratch -> coalesced STG ---
    {
        const int wq = wid & 3;
        const int colh = (wid >> 2) * 64;
        const uint32_t toff = tbase + ((uint32_t)wq << 21) + (uint32_t)colh;

        uint32_t dr[64];
        ld_tm32(dr,      toff);
        ld_tm32(dr + 32, toff + 32);
        TC_WAIT_LD();

        char* wsc = smem + (sb - sbRaw) + TC_HDR + wid * EP_WSTRIDE;
        const int cbase = col0 + colh;
        const int r = row0 + wq * 32 + lane;
        const size_t gbase = (size_t)(row0 + wq * 32) * N + cbase;

        if (EPI == EPI_NONE || EPI == EPI_BIAS) {
            #pragma unroll
            for (int j = 0; j < 64; j += 4) {
                float4 v;
                v.x = __uint_as_float(dr[j + 0]);
                v.y = __uint_as_float(dr[j + 1]);
                v.z = __uint_as_float(dr[j + 2]);
                v.w = __uint_as_float(dr[j + 3]);
                if (EPI == EPI_BIAS) {
                    v.x += bias[cbase + j];     v.y += bias[cbase + j + 1];
                    v.z += bias[cbase + j + 2]; v.w += bias[cbase + j + 3];
                }
                *(float4*)(wsc + lane * 272 + j * 4) = v;
            }
            __syncwarp();
            float* Cb = Cg + (size_t)bz * sC;
            #pragma unroll
            for (int it = 0; it < 16; it++) {
                int rr = it * 2 + (lane >> 4);
                int ch = (lane & 15) * 16;
                float4 v = *(float4*)(wsc + rr * 272 + ch);
                *(float4*)((char*)(Cb + gbase + (size_t)rr * N) + ch) = v;
            }
        } else {
            float inv = (EPI == EPI_SC_SPLIT) ? 1.0f / (float)(r + 1) : 0.f;
            #pragma unroll
            for (int j = 0; j < 64; j += 2) {
                float x0 = __uint_as_float(dr[j]);
                float x1 = __uint_as_float(dr[j + 1]);
                if (EPI == EPI_BR_SPLIT) {
                    x0 = fmaxf(x0 + bias[cbase + j], 0.f);
                    x1 = fmaxf(x1 + bias[cbase + j + 1], 0.f);
                } else if (EPI == EPI_SC_SPLIT) {
                    x0 = (cbase + j     <= r) ? fmaxf(x0, 0.f) * inv : 0.f;
                    x1 = (cbase + j + 1 <= r) ? fmaxf(x1, 0.f) * inv : 0.f;
                }
                bf16 h0, l0, h1, l1;
                split1(x0, h0, l0); split1(x1, h1, l1);
                __nv_bfloat162 vh; vh.x = h0; vh.y = h1;
                __nv_bfloat162 vl; vl.x = l0; vl.y = l1;
                *(__nv_bfloat162*)(wsc + lane * 144 + j * 2)        = vh;
                *(__nv_bfloat162*)(wsc + 4608 + lane * 144 + j * 2) = vl;
            }
            __syncwarp();
            bf16* ChB = Chg + (size_t)bz * sC;
            bf16* ClB = Clg + (size_t)bz * sC;
            #pragma unroll
            for (int it = 0; it < 8; it++) {
                int rr = it * 4 + (lane >> 3);
                int ch = (lane & 7) * 16;
                uint4 vH = *(uint4*)(wsc + rr * 144 + ch);
                uint4 vL = *(uint4*)(wsc + 4608 + rr * 144 + ch);
                *(uint4*)((char*)(ChB + gbase + (size_t)rr * N) + ch) = vH;
                *(uint4*)((char*)(ClB + gbase + (size_t)rr * N) + ch) = vL;
            }
        }
    }

    __syncthreads();
    if (wid == 0)
        asm volatile("tcgen05.dealloc.cta_group::1.sync.aligned.b32 %0, %1;"
                     :: "r"(tbase), "r"((uint32_t)TMEM_COLS_ALLOC));

#else
    // ======================= mma.sync fallback body ==========================
    const uint32_t smBase = cvs(smem);
    const int NT = Keff / FB_BK;

    float acc[2][8][4];
    #pragma unroll
    for (int i = 0; i < 2; i++)
        #pragma unroll
        for (int j = 0; j < 8; j++)
            #pragma unroll
            for (int q = 0; q < 4; q++) acc[i][j][q] = 0.f;

    const int wm = wid >> 1, wn = wid & 1;
    const int lr = lane & 15;
    const uint32_t colo = (uint32_t)(lane >> 4) * 16;

    #pragma unroll
    for (int s = 0; s < FB_STAGES - 1; s++) {
        if (s < NT) fb_load_stage(smBase + s * FB_STG, Ah, Al, Bh, Bl, K, s * FB_BK, row0, col0, tid);
        CP_COMMIT();
    }

    for (int t = 0; t < NT; t++) {
        CP_WAIT1();
        __syncthreads();

        int tp = t + FB_STAGES - 1;
        if (tp < NT)
            fb_load_stage(smBase + (tp % FB_STAGES) * FB_STG, Ah, Al, Bh, Bl, K, tp * FB_BK, row0, col0, tid);
        CP_COMMIT();

        const uint32_t stg = smBase + (t % FB_STAGES) * FB_STG;
        const uint32_t aRow = stg + (uint32_t)(wm * 32 + lr) * 80 + colo;
        const uint32_t bRow = stg + 2 * FB_PL + (uint32_t)(wn * 64 + lr) * 80 + colo;

        #pragma unroll
        for (int kk = 0; kk < 2; kk++) {
            const uint32_t ka = aRow + kk * 32, kb = bRow + kk * 32;
            uint32_t ah[2][4], al[2][4];
            #pragma unroll
            for (int mf = 0; mf < 2; mf++) {
                ldsm4(ah[mf], ka + mf * 16 * 80);
                ldsm4(al[mf], ka + FB_PL + mf * 16 * 80);
            }
            uint32_t bh[4][4], blf[4][4];
            #pragma unroll
            for (int g = 0; g < 4; g++) {
                ldsm4(bh[g], kb + g * 16 * 80);
                ldsm4(blf[g], kb + FB_PL + g * 16 * 80);
            }
            #pragma unroll
            for (int mf = 0; mf < 2; mf++) {
                #pragma unroll
                for (int g = 0; g < 4; g++) {
                    mma16816(acc[mf][2 * g],     ah[mf], bh[g][0],  bh[g][2]);
                    mma16816(acc[mf][2 * g],     ah[mf], blf[g][0], blf[g][2]);
                    mma16816(acc[mf][2 * g],     al[mf], bh[g][0],  bh[g][2]);
                    mma16816(acc[mf][2 * g + 1], ah[mf], bh[g][1],  bh[g][3]);
                    mma16816(acc[mf][2 * g + 1], ah[mf], blf[g][1], blf[g][3]);
                    mma16816(acc[mf][2 * g + 1], al[mf], bh[g][1],  bh[g][3]);
                }
            }
        }
        __syncthreads();
    }
    CP_WAIT0();

    float*  C  = (EPI == EPI_NONE || EPI == EPI_BIAS) ? Cg + (size_t)bz * sC : nullptr;
    bf16*   Ch = (EPI >= EPI_SPLIT) ? Chg + (size_t)bz * sC : nullptr;
    bf16*   Cl = (EPI >= EPI_SPLIT) ? Clg + (size_t)bz * sC : nullptr;
    const int qr = lane >> 2, qc = (lane & 3) * 2;
    #pragma unroll
    for (int mf = 0; mf < 2; mf++) {
        #pragma unroll
        for (int nf = 0; nf < 8; nf++) {
            int rA = row0 + wm * 32 + mf * 16 + qr;
            int cb = col0 + wn * 64 + nf * 8 + qc;
            #pragma unroll
            for (int half = 0; half < 2; half++) {
                int r = rA + half * 8;
                float x0 = acc[mf][nf][half * 2 + 0];
                float x1 = acc[mf][nf][half * 2 + 1];
                if (EPI == EPI_BIAS) {
                    x0 += bias[cb]; x1 += bias[cb + 1];
                } else if (EPI == EPI_BR_SPLIT) {
                    x0 = fmaxf(x0 + bias[cb], 0.f);
                    x1 = fmaxf(x1 + bias[cb + 1], 0.f);
                } else if (EPI == EPI_SC_SPLIT) {
                    float inv = 1.0f / (float)(r + 1);
                    x0 = (cb     <= r) ? fmaxf(x0, 0.f) * inv : 0.f;
                    x1 = (cb + 1 <= r) ? fmaxf(x1, 0.f) * inv : 0.f;
                }
                if (EPI == EPI_NONE || EPI == EPI_BIAS) {
                    float2 v; v.x = x0; v.y = x1;
                    *(float2*)&C[(size_t)r * N + cb] = v;
                } else {
                    bf16 h0, l0, h1, l1;
                    split1(x0, h0, l0); split1(x1, h1, l1);
                    __nv_bfloat162 vh; vh.x = h0; vh.y = h1;
                    __nv_bfloat162 vl; vl.x = l0; vl.y = l1;
                    *(__nv_bfloat162*)&Ch[(size_t)r * N + cb] = vh;
                    *(__nv_bfloat162*)&Cl[(size_t)r * N + cb] = vl;
                }
            }
        }
    }
#endif
}

// ---------------------------------------------------------------------------
// Transpose + split-convert: in[z][R][C] fp32 -> oh/ol[z][C][R] bf16
// ---------------------------------------------------------------------------
__global__ void convT_k(const float* __restrict__ in, bf16* __restrict__ oh,
                        bf16* __restrict__ ol, int R, int C)
{
    const int z = blockIdx.z;
    in += (size_t)z * R * C;
    oh += (size_t)z * R * C;
    ol += (size_t)z * R * C;
    __shared__ float t[32][33];
    const int c0 = blockIdx.x * 32, r0 = blockIdx.y * 32;
    const int tx = threadIdx.x, ty = threadIdx.y;
    #pragma unroll
    for (int i = 0; i < 4; i++)
        t[ty + i * 8][tx] = in[(size_t)(r0 + ty + i * 8) * C + c0 + tx];
    __syncthreads();
    #pragma unroll
    for (int i = 0; i < 4; i++) {
        float v = t[tx][ty + i * 8];
        int cc = c0 + ty + i * 8, rr = r0 + tx;
        bf16 h, l; split1(v, h, l);
        oh[(size_t)cc * R + rr] = h;
        ol[(size_t)cc * R + rr] = l;
    }
}

// ---------------------------------------------------------------------------
// Fused residual + LayerNorm: x = (Hh+Hl) + Res; write LN(x) as hi/lo planes
// ---------------------------------------------------------------------------
__global__ void ln_k(const float* __restrict__ Res,
                     const float* __restrict__ g, const float* __restrict__ be,
                     bf16* __restrict__ Hh, bf16* __restrict__ Hl)
{
    int row = blockIdx.x;
    int tid = threadIdx.x;
    int lane = tid & 31, warp = tid >> 5;
    __shared__ float sm[8];
    const size_t base = (size_t)row * EB + tid * 4;

    __nv_bfloat162 h01 = *(__nv_bfloat162*)&Hh[base];
    __nv_bfloat162 h23 = *(__nv_bfloat162*)&Hh[base + 2];
    __nv_bfloat162 l01 = *(__nv_bfloat162*)&Hl[base];
    __nv_bfloat162 l23 = *(__nv_bfloat162*)&Hl[base + 2];
    float4 rr = *(const float4*)&Res[base];
    float4 x;
    x.x = __bfloat162float(h01.x) + __bfloat162float(l01.x) + rr.x;
    x.y = __bfloat162float(h01.y) + __bfloat162float(l01.y) + rr.y;
    x.z = __bfloat162float(h23.x) + __bfloat162float(l23.x) + rr.z;
    x.w = __bfloat162float(h23.y) + __bfloat162float(l23.y) + rr.w;

    float s = x.x + x.y + x.z + x.w;
    #pragma unroll
    for (int o = 16; o; o >>= 1) s += __shfl_down_sync(0xffffffffu, s, o);
    if (!lane) sm[warp] = s;
    __syncthreads();
    float mu;
    {
        float t = (lane < 8) ? sm[lane] : 0.f;
        #pragma unroll
        for (int o = 4; o; o >>= 1) t += __shfl_down_sync(0xffffffffu, t, o);
        mu = __shfl_sync(0xffffffffu, t, 0) * (1.0f / 1024.0f);
    }
    __syncthreads();

    float dx0 = x.x - mu, dx1 = x.y - mu, dx2 = x.z - mu, dx3 = x.w - mu;
    float sq = dx0 * dx0 + dx1 * dx1 + dx2 * dx2 + dx3 * dx3;
    #pragma unroll
    for (int o = 16; o; o >>= 1) sq += __shfl_down_sync(0xffffffffu, sq, o);
    if (!lane) sm[warp] = sq;
    __syncthreads();
    float rstd;
    {
        float t = (lane < 8) ? sm[lane] : 0.f;
        #pragma unroll
        for (int o = 4; o; o >>= 1) t += __shfl_down_sync(0xffffffffu, t, o);
        float var = __shfl_sync(0xffffffffu, t, 0) * (1.0f / 1024.0f);
        rstd = rsqrtf(var + 1e-5f);
    }

    float4 gv = *(const float4*)&g[tid * 4];
    float4 bv = *(const float4*)&be[tid * 4];
    float4 o;
    o.x = dx0 * rstd * gv.x + bv.x;
    o.y = dx1 * rstd * gv.y + bv.y;
    o.z = dx2 * rstd * gv.z + bv.z;
    o.w = dx3 * rstd * gv.w + bv.w;

    bf16 h0, l0, h1, l1, h2, l2, h3, l3;
    split1(o.x, h0, l0); split1(o.y, h1, l1);
    split1(o.z, h2, l2); split1(o.w, h3, l3);
    __nv_bfloat162 a0; a0.x = h0; a0.y = h1;
    __nv_bfloat162 a1; a1.x = h2; a1.y = h3;
    __nv_bfloat162 b0; b0.x = l0; b0.y = l1;
    __nv_bfloat162 b1; b1.x = l2; b1.y = l3;
    *(__nv_bfloat162*)&Hh[base]     = a0;
    *(__nv_bfloat162*)&Hh[base + 2] = a1;
    *(__nv_bfloat162*)&Hl[base]     = b0;
    *(__nv_bfloat162*)&Hl[base + 2] = b1;
}

// ---------------------------------------------------------------------------
// Embedding
// ---------------------------------------------------------------------------
__global__ void aw_k(const float* __restrict__ act, const float* __restrict__ Wemb,
                     float* __restrict__ aW)
{
    int e = blockIdx.x * 128 + threadIdx.x;
    int b = blockIdx.y;
    const float* a = act + (size_t)b * DA;
    float s = 0.f;
    #pragma unroll 4
    for (int i = 0; i < DA; i++)
        s = fmaf(a[i], Wemb[(size_t)i * EB + e], s);
    aW[(size_t)b * EB + e] = s;
}

__global__ void build_hs_k(const float* __restrict__ aW, const float* __restrict__ Wemb,
                           const float* __restrict__ bemb, const float* __restrict__ wpe,
                           bf16* __restrict__ Hh, bf16* __restrict__ Hl)
{
    int row = blockIdx.x;
    int n = row & (SEQ - 1), b = row >> 10;
    int e = threadIdx.x * 4;
    float4 w1 = *(const float4*)&Wemb[(size_t)651 * EB + e];
    float4 w2 = *(const float4*)&Wemb[(size_t)652 * EB + e];
    float4 bb = *(const float4*)&bemb[e];
    float4 pp = *(const float4*)&wpe[(size_t)n * EB + e];
    float pos = (float)(n + 1);
    float4 v;
    v.x = w1.x + pos * w2.x + bb.x + pp.x;
    v.y = w1.y + pos * w2.y + bb.y + pp.y;
    v.z = w1.z + pos * w2.z + bb.z + pp.z;
    v.w = w1.w + pos * w2.w + bb.w + pp.w;
    if (!(n & 1)) {
        float4 av = *(const float4*)&aW[(size_t)b * EB + e];
        v.x += av.x; v.y += av.y; v.z += av.z; v.w += av.w;
    }
    const size_t base = (size_t)row * EB + e;
    bf16 h, l;
    split1(v.x, h, l); Hh[base + 0] = h; Hl[base + 0] = l;
    split1(v.y, h, l); Hh[base + 1] = h; Hl[base + 1] = l;
    split1(v.z, h, l); Hh[base + 2] = h; Hl[base + 2] = l;
    split1(v.w, h, l); Hh[base + 3] = h; Hl[base + 3] = l;
}

// ---------------------------------------------------------------------------
// Prediction head (reads hi/lo planes)
// ---------------------------------------------------------------------------
__global__ void pred_k(const bf16* __restrict__ Hh, const bf16* __restrict__ Hl,
                       const float* __restrict__ Wp,
                       const float* __restrict__ bp, float* __restrict__ out)
{
    int idx = blockIdx.x;
    int b = idx >> 9, h = idx & 511;
    const size_t base = ((size_t)(b * SEQ + 2 * h)) * EB;
    int tid = threadIdx.x, lane = tid & 31, warp = tid >> 5;

    __nv_bfloat162 h01 = *(__nv_bfloat162*)&Hh[base + tid * 4];
    __nv_bfloat162 h23 = *(__nv_bfloat162*)&Hh[base + tid * 4 + 2];
    __nv_bfloat162 l01 = *(__nv_bfloat162*)&Hl[base + tid * 4];
    __nv_bfloat162 l23 = *(__nv_bfloat162*)&Hl[base + tid * 4 + 2];
    float xs[4];
    xs[0] = __bfloat162float(h01.x) + __bfloat162float(l01.x);
    xs[1] = __bfloat162float(h01.y) + __bfloat162float(l01.y);
    xs[2] = __bfloat162float(h23.x) + __bfloat162float(l23.x);
    xs[3] = __bfloat162float(h23.y) + __bfloat162float(l23.y);
    const float* w0 = Wp + (size_t)(tid * 4) * AD;

    float p[AD];
    #pragma unroll
    for (int ad = 0; ad < AD; ++ad) p[ad] = 0.f;
    #pragma unroll
    for (int t = 0; t < 4; t++)
        #pragma unroll
        for (int ad = 0; ad < AD; ++ad)
            p[ad] = fmaf(xs[t], w0[t * AD + ad], p[ad]);

    __shared__ float red[8][AD];
    #pragma unroll
    for (int ad = 0; ad < AD; ad++) {
        float s = p[ad];
        #pragma unroll
        for (int o = 16; o; o >>= 1) s += __shfl_down_sync(0xffffffffu, s, o);
        if (!lane) red[warp][ad] = s;
    }
    __syncthreads();
    if (tid < AD) {
        float s = 0.f;
        #pragma unroll
        for (int w = 0; w < 8; w++) s += red[w][tid];
        out[(size_t)idx * AD + tid] = s + bp[tid];
    }
}

// ---------------------------------------------------------------------------
extern "C" void kernel_launch(void* const* d_in, const int* in_sizes, int n_in,
                              void* d_out, int out_size)
{
    const float* action_set = (const float*)d_in[0];
    const float* wpe    = (const float*)d_in[2];
    const float* W_emb  = (const float*)d_in[3];
    const float* b_emb  = (const float*)d_in[4];
    const float* Wq     = (const float*)d_in[5];
    const float* Wk     = (const float*)d_in[6];
    const float* Wv     = (const float*)d_in[7];
    const float* ln1_g  = (const float*)d_in[8];
    const float* ln1_b  = (const float*)d_in[9];
    const float* W1     = (const float*)d_in[10];
    const float* b1     = (const float*)d_in[11];
    const float* W2     = (const float*)d_in[12];
    const float* b2     = (const float*)d_in[13];
    const float* ln2_g  = (const float*)d_in[14];
    const float* ln2_b  = (const float*)d_in[15];
    const float* W_pred = (const float*)d_in[16];
    const float* b_pred = (const float*)d_in[17];
    float* out = (float*)d_out;

    float *T, *aW;
    cudaGetSymbolAddress((void**)&T,  d_T);
    cudaGetSymbolAddress((void**)&aW, d_aW);
    bf16 *Hh, *Hl, *Qh, *Ql, *Kh, *Kl, *Vth, *Vtl, *Sh, *Sl;
    cudaGetSymbolAddress((void**)&Hh, d_Hh);   cudaGetSymbolAddress((void**)&Hl, d_Hl);
    cudaGetSymbolAddress((void**)&Qh, d_Qh);   cudaGetSymbolAddress((void**)&Ql, d_Ql);
    cudaGetSymbolAddress((void**)&Kh, d_Kh);   cudaGetSymbolAddress((void**)&Kl, d_Kl);
    cudaGetSymbolAddress((void**)&Vth, d_Vth); cudaGetSymbolAddress((void**)&Vtl, d_Vtl);
    cudaGetSymbolAddress((void**)&Sh, d_Sh);   cudaGetSymbolAddress((void**)&Sl, d_Sl);
    bf16 *Wqh, *Wql, *Wkh, *Wkl, *Wvh, *Wvl, *W1h, *W1l, *W2h, *W2l;
    cudaGetSymbolAddress((void**)&Wqh, d_Wq_h); cudaGetSymbolAddress((void**)&Wql, d_Wq_l);
    cudaGetSymbolAddress((void**)&Wkh, d_Wk_h); cudaGetSymbolAddress((void**)&Wkl, d_Wk_l);
    cudaGetSymbolAddress((void**)&Wvh, d_Wv_h); cudaGetSymbolAddress((void**)&Wvl, d_Wv_l);
    cudaGetSymbolAddress((void**)&W1h, d_W1_h); cudaGetSymbolAddress((void**)&W1l, d_W1_l);
    cudaGetSymbolAddress((void**)&W2h, d_W2_h); cudaGetSymbolAddress((void**)&W2l, d_W2_l);

    cudaFuncSetAttribute(gemm_k<EPI_SPLIT,    false>, cudaFuncAttributeMaxDynamicSharedMemorySize, SMB);
    cudaFuncSetAttribute(gemm_k<EPI_SC_SPLIT, false>, cudaFuncAttributeMaxDynamicSharedMemorySize, SMB);
    cudaFuncSetAttribute(gemm_k<EPI_NONE,     true >, cudaFuncAttributeMaxDynamicSharedMemorySize, SMB);
    cudaFuncSetAttribute(gemm_k<EPI_BR_SPLIT, false>, cudaFuncAttributeMaxDynamicSharedMemorySize, SMB);
    cudaFuncSetAttribute(gemm_k<EPI_BIAS,     false>, cudaFuncAttributeMaxDynamicSharedMemorySize, SMB);

    const dim3 cw(EB / 32, EB / 32, NLAY);
    const dim3 ct(32, 8);
    const dim3 gBig(EB / BN, MTOT / BM, 1);       // (8, 128)
    const dim3 gAtt(SEQ / BN, SEQ / BM, NBAT);    // (8, 8, 16)
    const dim3 gVt (SEQ / BN, EB / BM, NBAT);     // (8, 8, 16)
    const size_t sNE = (size_t)SEQ * EB;
    const size_t sSS = (size_t)SEQ * SEQ;
    const size_t sW  = (size_t)EB * EB;

    // weight transpose + split (once per call)
    convT_k<<<cw, ct>>>(Wq, Wqh, Wql, EB, EB);
    convT_k<<<cw, ct>>>(Wk, Wkh, Wkl, EB, EB);
    convT_k<<<cw, ct>>>(Wv, Wvh, Wvl, EB, EB);
    convT_k<<<cw, ct>>>(W1, W1h, W1l, EB, EB);
    convT_k<<<cw, ct>>>(W2, W2h, W2l, EB, EB);

    // embedding
    aw_k<<<dim3(EB / 128, NBAT), 128>>>(action_set, W_emb, aW);
    build_hs_k<<<MTOT, 256>>>(aW, W_emb, b_emb, wpe, Hh, Hl);

    for (int l = 0; l < NLAY; ++l) {
        const size_t lw = (size_t)l * sW;
        // Q = H Wq,  K = H Wk   (split outputs)
        gemm_k<EPI_SPLIT, false><<<gBig, 256, SMB>>>(Hh, Hl, Wqh + lw, Wql + lw,
            nullptr, nullptr, Qh, Ql, EB, EB, 0, 0, 0);
        gemm_k<EPI_SPLIT, false><<<gBig, 256, SMB>>>(Hh, Hl, Wkh + lw, Wkl + lw,
            nullptr, nullptr, Kh, Kl, EB, EB, 0, 0, 0);
        // V^T directly: Vt[e,s] = sum_k Wv[k,e] H[s,k]
        gemm_k<EPI_SPLIT, false><<<gVt, 256, SMB>>>(Wvh + lw, Wvl + lw, Hh, Hl,
            nullptr, nullptr, Vth, Vtl, SEQ, EB, 0, sNE, sNE);
        // S = relu(Q K^T) * mask  (above-diagonal tiles skipped)
        gemm_k<EPI_SC_SPLIT, false><<<gAtt, 256, SMB>>>(Qh, Ql, Kh, Kl,
            nullptr, nullptr, Sh, Sl, SEQ, EB, sNE, sNE, sSS);
        // T = S V (triangular K-loop)
        gemm_k<EPI_NONE, true><<<gAtt, 256, SMB>>>(Sh, Sl, Vth, Vtl,
            nullptr, T, nullptr, nullptr, EB, SEQ, sSS, sNE, sNE);
        ln_k<<<MTOT, 256>>>(T, ln1_g + (size_t)l * EB, ln1_b + (size_t)l * EB, Hh, Hl);
        gemm_k<EPI_BR_SPLIT, false><<<gBig, 256, SMB>>>(Hh, Hl, W1h + lw, W1l + lw,
            b1 + (size_t)l * EB, nullptr, Sh, Sl, EB, EB, 0, 0, 0);
        gemm_k<EPI_BIAS, false><<<gBig, 256, SMB>>>(Sh, Sl, W2h + lw, W2l + lw,
            b2 + (size_t)l * EB, T, nullptr, nullptr, EB, EB, 0, 0, 0);
        ln_k<<<MTOT, 256>>>(T, ln2_g + (size_t)l * EB, ln2_b + (size_t)l * EB, Hh, Hl);
    }

    pred_k<<<NBAT * HORZ, 256>>>(Hh, Hl, W_pred, b_pred, out);
}